// round 3
// baseline (speedup 1.0000x reference)
#include <cuda_runtime.h>
#include <cuda_bf16.h>
#include <math.h>

// Problem constants (fixed instance)
#define NN    8192
#define BB    32
#define NMAX  512
#define FF    128
#define HH    512
#define LL    3
#define GG    8
#define HFF   2048
#define EE    131072
#define HG    (HH/GG)    // 64
#define HFG   (HFF/GG)   // 256
#define ADJW  16         // 512 bits / 32
#define ADJTOT ((size_t)BB*NMAX*ADJW)

#define FLAG_ACC 1
#define FLAG_SIG 2

// -------------------- scratch (device globals; no allocs) --------------------
__device__ __align__(16) float    g_h  [NN*HH];
__device__ __align__(16) float    g_hg [NN*HH];
__device__ __align__(16) float    g_qk [NN*HH];
__device__ __align__(16) float    g_att[NN*HH];
__device__ __align__(16) float    g_out[NN*HH];
__device__ __align__(16) float    g_hn [NN*HH];
__device__ __align__(16) float    g_up [NN*HFF];
__device__ __align__(16) float    g_dn [NN*HH];
__device__ float    g_deg[NN];
__device__ int      g_starts[BB+1];
__device__ int      g_pos[NN];
__device__ unsigned g_adj[ADJTOT];

__device__ __forceinline__ float sigf(float x){ return 1.f/(1.f+__expf(-x)); }

// -------------------- graph structure --------------------
__global__ void clear_adj_k(unsigned* __restrict__ adj){
    size_t i = (size_t)blockIdx.x*blockDim.x + threadIdx.x;
    if (i < ADJTOT) adj[i] = 0u;
}

__global__ void starts_k(const int* __restrict__ batch, int* __restrict__ starts){
    int n = blockIdx.x*blockDim.x + threadIdx.x;
    if (n >= NN) return;
    if (n == 0){ starts[batch[0]] = 0; starts[BB] = NN; }
    else if (batch[n] != batch[n-1]) starts[batch[n]] = n;
}

__global__ void pos_self_k(const int* __restrict__ batch, const int* __restrict__ starts,
                           int* __restrict__ pos, unsigned* __restrict__ adj){
    int n = blockIdx.x*blockDim.x + threadIdx.x;
    if (n >= NN) return;
    int b = batch[n];
    int p = n - starts[b];
    pos[n] = p;
    atomicOr(&adj[((size_t)b*NMAX + p)*ADJW + (p>>5)], 1u << (p&31));
}

__global__ void edge_k(const int* __restrict__ ei, const int* __restrict__ batch,
                       const int* __restrict__ pos, unsigned* __restrict__ adj){
    int e = blockIdx.x*blockDim.x + threadIdx.x;
    if (e >= EE) return;
    int s = ei[e];
    int d = ei[EE + e];
    int b = batch[s];
    int ps = pos[s], pd = pos[d];
    atomicOr(&adj[((size_t)b*NMAX + ps)*ADJW + (pd>>5)], 1u << (pd&31));
}

__global__ void deg_k(const int* __restrict__ batch, const int* __restrict__ pos,
                      const unsigned* __restrict__ adj, float* __restrict__ deg){
    int n = blockIdx.x*blockDim.x + threadIdx.x;
    if (n >= NN) return;
    int b = batch[n];
    const unsigned* row = adj + ((size_t)b*NMAX + pos[n])*ADJW;
    int c = 0;
    #pragma unroll
    for (int w = 0; w < ADJW; w++) c += __popc(row[w]);
    deg[n] = (float)c;
}

// -------------------- generic fp32 GEMM: C[=|+=] A@W (+bias) (sigmoid?) --------------------
// A: row-major [M,K] ld=lda, W: row-major [K,N] ld=ldw, C: row-major ld=ldc.
// grid: (N/64, M/64, groups); per-group pointer offsets via strides.
__global__ void __launch_bounds__(256)
gemm_k(const float* __restrict__ A, int lda, long long sAz,
       const float* __restrict__ W, int ldw, long long sWz,
       float*       __restrict__ C, int ldc, long long sCz,
       const float* __restrict__ bias, long long sBz,
       int K, int flags)
{
    A += (size_t)blockIdx.z * sAz;
    W += (size_t)blockIdx.z * sWz;
    C += (size_t)blockIdx.z * sCz;
    if (bias) bias += (size_t)blockIdx.z * sBz;

    __shared__ float As[16][64];
    __shared__ float Bs[16][64];

    int tid  = threadIdx.x;
    int row0 = blockIdx.y * 64;
    int col0 = blockIdx.x * 64;
    int arow = tid >> 2,  ak   = (tid & 3)  * 4;
    int brow = tid >> 4,  bcol = (tid & 15) * 4;
    int ty   = tid >> 4,  tx   = tid & 15;

    float acc[4][4] = {};

    for (int k0 = 0; k0 < K; k0 += 16){
        float4 a = *(const float4*)(A + (size_t)(row0 + arow)*lda + k0 + ak);
        As[ak+0][arow] = a.x; As[ak+1][arow] = a.y;
        As[ak+2][arow] = a.z; As[ak+3][arow] = a.w;
        float4 bv = *(const float4*)(W + (size_t)(k0 + brow)*ldw + col0 + bcol);
        *(float4*)&Bs[brow][bcol] = bv;
        __syncthreads();
        #pragma unroll
        for (int k = 0; k < 16; k++){
            float4 av = *(const float4*)&As[k][ty*4];
            float4 bw = *(const float4*)&Bs[k][tx*4];
            float aa[4] = {av.x, av.y, av.z, av.w};
            float bb[4] = {bw.x, bw.y, bw.z, bw.w};
            #pragma unroll
            for (int i = 0; i < 4; i++)
                #pragma unroll
                for (int j = 0; j < 4; j++)
                    acc[i][j] += aa[i]*bb[j];
        }
        __syncthreads();
    }

    #pragma unroll
    for (int i = 0; i < 4; i++){
        size_t r = (size_t)(row0 + ty*4 + i);
        #pragma unroll
        for (int j = 0; j < 4; j++){
            int c = col0 + tx*4 + j;
            float v = acc[i][j];
            if (bias)           v += bias[c];
            if (flags & FLAG_ACC) v += C[r*ldc + c];
            if (flags & FLAG_SIG) v = sigf(v);
            C[r*ldc + c] = v;
        }
    }
}

// -------------------- elementwise / reductions --------------------
__global__ void gate_k(const float* __restrict__ h, const float* __restrict__ deg,
                       const float* __restrict__ Wd, const float* __restrict__ bd,
                       float* __restrict__ hg){
    int n = blockIdx.x, t = threadIdx.x;  // 128 threads, float4 each
    float d = deg[n];
    float4 hv = ((const float4*)(h + (size_t)n*HH))[t];
    float4 wv = ((const float4*)Wd)[t];
    float4 bv = ((const float4*)bd)[t];
    float4 o;
    o.x = hv.x * sigf(d*wv.x + bv.x);
    o.y = hv.y * sigf(d*wv.y + bv.y);
    o.z = hv.z * sigf(d*wv.z + bv.z);
    o.w = hv.w * sigf(d*wv.w + bv.w);
    ((float4*)(hg + (size_t)n*HH))[t] = o;
}

// sparse masked attention: warp per node
__global__ void attn_k(const float* __restrict__ qk, const float* __restrict__ hg,
                       const unsigned* __restrict__ adj, const int* __restrict__ starts,
                       const int* __restrict__ batch, float* __restrict__ out){
    int warp = (blockIdx.x*blockDim.x + threadIdx.x) >> 5;
    int lane = threadIdx.x & 31;
    if (warp >= NN) return;
    int n = warp;
    int b = batch[n];
    int start = starts[b];
    int p = n - start;
    const unsigned* row = adj + ((size_t)b*NMAX + p)*ADJW;
    const float4* qn4 = (const float4*)(qk + (size_t)n*HH);
    float4 qn[4];
    #pragma unroll
    for (int c = 0; c < 4; c++) qn[c] = qn4[lane + c*32];
    float4 acc[4] = {{0,0,0,0},{0,0,0,0},{0,0,0,0},{0,0,0,0}};
    float rowsum = 0.f;
    const float inv_sqrt_h = 0.044194173824159216f; // 1/sqrt(512)

    for (int w = 0; w < ADJW; w++){
        unsigned bits = row[w];
        while (bits){
            int t = __ffs((int)bits) - 1; bits &= bits - 1;
            int m = start + w*32 + t;
            const float4* qm4 = (const float4*)(qk + (size_t)m*HH);
            float s = 0.f;
            #pragma unroll
            for (int c = 0; c < 4; c++){
                float4 v = qm4[lane + c*32];
                s += qn[c].x*v.x + qn[c].y*v.y + qn[c].z*v.z + qn[c].w*v.w;
            }
            #pragma unroll
            for (int o = 16; o; o >>= 1) s += __shfl_xor_sync(0xffffffffu, s, o);
            s *= inv_sqrt_h;
            rowsum += s;
            const float4* hm4 = (const float4*)(hg + (size_t)m*HH);
            #pragma unroll
            for (int c = 0; c < 4; c++){
                float4 hv = hm4[lane + c*32];
                acc[c].x += s*hv.x; acc[c].y += s*hv.y;
                acc[c].z += s*hv.z; acc[c].w += s*hv.w;
            }
        }
    }
    float inv = 1.f/(rowsum + 1e-6f);
    float4* o4 = (float4*)(out + (size_t)n*HH);
    #pragma unroll
    for (int c = 0; c < 4; c++){
        acc[c].x *= inv; acc[c].y *= inv; acc[c].z *= inv; acc[c].w *= inv;
        o4[lane + c*32] = acc[c];
    }
}

// l2-normalize rows then relu
__global__ void l2relu_k(const float* __restrict__ x, float* __restrict__ y){
    int n = blockIdx.x, t = threadIdx.x; // 128 threads, float4 each
    float4 v = ((const float4*)(x + (size_t)n*HH))[t];
    float ss = v.x*v.x + v.y*v.y + v.z*v.z + v.w*v.w;
    #pragma unroll
    for (int o = 16; o; o >>= 1) ss += __shfl_xor_sync(0xffffffffu, ss, o);
    __shared__ float sh[4];
    __shared__ float sinv;
    int w = t >> 5, l = t & 31;
    if (l == 0) sh[w] = ss;
    __syncthreads();
    if (t == 0){
        float tot = sh[0] + sh[1] + sh[2] + sh[3];
        sinv = 1.f / fmaxf(sqrtf(tot), 1e-12f);
    }
    __syncthreads();
    float iv = sinv;
    float4 o;
    o.x = fmaxf(v.x*iv, 0.f); o.y = fmaxf(v.y*iv, 0.f);
    o.z = fmaxf(v.z*iv, 0.f); o.w = fmaxf(v.w*iv, 0.f);
    ((float4*)(y + (size_t)n*HH))[t] = o;
}

// layernorm over width W, NT threads/row; optional fused relu; in-place safe
template<int W, int NT, bool RELU>
__global__ void ln_k(const float* __restrict__ x, float* __restrict__ y,
                     const float* __restrict__ g, const float* __restrict__ b){
    constexpr int PT = W / NT;
    int row = blockIdx.x, t = threadIdx.x;
    const float* xr = x + (size_t)row*W;
    float*       yr = y + (size_t)row*W;
    float v[PT]; float s = 0.f, s2 = 0.f;
    #pragma unroll
    for (int i = 0; i < PT; i++){ float u = xr[t + i*NT]; v[i] = u; s += u; s2 += u*u; }
    #pragma unroll
    for (int o = 16; o; o >>= 1){
        s  += __shfl_xor_sync(0xffffffffu, s,  o);
        s2 += __shfl_xor_sync(0xffffffffu, s2, o);
    }
    __shared__ float sh[2][NT/32];
    __shared__ float mb[2];
    int w = t >> 5, l = t & 31;
    if (l == 0){ sh[0][w] = s; sh[1][w] = s2; }
    __syncthreads();
    if (t == 0){
        float ts = 0.f, ts2 = 0.f;
        #pragma unroll
        for (int i = 0; i < NT/32; i++){ ts += sh[0][i]; ts2 += sh[1][i]; }
        float mean = ts / W;
        float var  = ts2 / W - mean*mean;
        mb[0] = mean; mb[1] = rsqrtf(var + 1e-5f);
    }
    __syncthreads();
    float mean = mb[0], rstd = mb[1];
    #pragma unroll
    for (int i = 0; i < PT; i++){
        int c = t + i*NT;
        float o = (v[i] - mean) * rstd * g[c] + b[c];
        if (RELU) o = fmaxf(o, 0.f);
        yr[c] = o;
    }
}

__global__ void res_k(float* __restrict__ h, const float* __restrict__ dn,
                      const float* __restrict__ gamma){
    int n = blockIdx.x, t = threadIdx.x;
    float4 hv = ((const float4*)(h + (size_t)n*HH))[t];
    float4 dv = ((const float4*)(dn + (size_t)n*HH))[t];
    float4 gm = ((const float4*)gamma)[t];
    hv.x += gm.x*dv.x; hv.y += gm.y*dv.y; hv.z += gm.z*dv.z; hv.w += gm.w*dv.w;
    ((float4*)(h + (size_t)n*HH))[t] = hv;
}

__global__ void pool_k(const float* __restrict__ h, const int* __restrict__ starts,
                       float* __restrict__ out){
    int b = blockIdx.x;
    int f = blockIdx.y*128 + threadIdx.x;
    int s = starts[b], e = starts[b+1];
    float acc = 0.f;
    for (int n = s; n < e; n++) acc += h[(size_t)n*HH + f];
    out[(size_t)b*HH + f] = acc;
}

// -------------------- launcher --------------------
extern "C" void kernel_launch(void* const* d_in, const int* in_sizes, int n_in,
                              void* d_out, int out_size){
    const float* x     = (const float*)d_in[0];
    const int*   ei    = (const int*)d_in[1];     // int32 per harness dtype contract
    const int*   batch = (const int*)d_in[2];     // int32 per harness dtype contract
    const float* W_in = (const float*)d_in[3];
    const float* b_in = (const float*)d_in[4];
    const float* Wqk  = (const float*)d_in[5];
    const float* bqk  = (const float*)d_in[6];
    const float* Wd   = (const float*)d_in[7];
    const float* bd   = (const float*)d_in[8];
    const float* Wl   = (const float*)d_in[9];
    const float* bl   = (const float*)d_in[10];
    const float* Wr   = (const float*)d_in[11];
    const float* gamma= (const float*)d_in[12];
    const float* ln_g = (const float*)d_in[13];
    const float* ln_b = (const float*)d_in[14];
    const float* up_w = (const float*)d_in[15];
    const float* up_b = (const float*)d_in[16];
    const float* up_lg= (const float*)d_in[17];
    const float* up_lb= (const float*)d_in[18];
    const float* dn_w = (const float*)d_in[19];
    const float* dn_b = (const float*)d_in[20];
    const float* dn_lg= (const float*)d_in[21];
    const float* dn_lb= (const float*)d_in[22];
    float* out = (float*)d_out;

    float *h, *hg, *qk, *att, *ob, *hn, *up, *dn, *deg;
    int *starts, *pos; unsigned* adj;
    cudaGetSymbolAddress((void**)&h,   g_h);
    cudaGetSymbolAddress((void**)&hg,  g_hg);
    cudaGetSymbolAddress((void**)&qk,  g_qk);
    cudaGetSymbolAddress((void**)&att, g_att);
    cudaGetSymbolAddress((void**)&ob,  g_out);
    cudaGetSymbolAddress((void**)&hn,  g_hn);
    cudaGetSymbolAddress((void**)&up,  g_up);
    cudaGetSymbolAddress((void**)&dn,  g_dn);
    cudaGetSymbolAddress((void**)&deg, g_deg);
    cudaGetSymbolAddress((void**)&starts, g_starts);
    cudaGetSymbolAddress((void**)&pos,    g_pos);
    cudaGetSymbolAddress((void**)&adj,    g_adj);

    // graph structure (clear kernel instead of memset: graph-capturable on __device__ globals)
    clear_adj_k<<<(int)((ADJTOT + 255)/256), 256>>>(adj);
    starts_k  <<<NN/256, 256>>>(batch, starts);
    pos_self_k<<<NN/256, 256>>>(batch, starts, pos, adj);
    edge_k    <<<EE/256, 256>>>(ei, batch, pos, adj);
    deg_k     <<<NN/256, 256>>>(batch, pos, adj, deg);

    // h = x @ W_in + b_in
    gemm_k<<<dim3(HH/64, NN/64, 1), 256>>>(x, FF, 0, W_in, HH, 0, h, HH, 0, b_in, 0, FF, 0);

    for (int l = 0; l < LL; l++){
        gate_k<<<NN, 128>>>(h, deg, Wd + l*HH, bd + l*HH, hg);
        gemm_k<<<dim3(HH/64, NN/64, 1), 256>>>(hg, HH, 0, Wqk + (size_t)l*HH*HH, HH, 0,
                                               qk, HH, 0, bqk + l*HH, 0, HH, FLAG_SIG);
        attn_k<<<NN/8, 256>>>(qk, hg, adj, starts, batch, att);
        gemm_k<<<dim3(HH/64, NN/64, 1), 256>>>(att, HH, 0, Wl + (size_t)l*HH*HH, HH, 0,
                                               ob, HH, 0, bl + l*HH, 0, HH, 0);
        gemm_k<<<dim3(HH/64, NN/64, 1), 256>>>(hg, HH, 0, Wr + (size_t)l*HH*HH, HH, 0,
                                               ob, HH, 0, nullptr, 0, HH, FLAG_ACC);
        l2relu_k<<<NN, 128>>>(ob, h);
        ln_k<HH, 128, false><<<NN, 128>>>(h, hn, ln_g + l*HH, ln_b + l*HH);
        // grouped up: per group g: [N,64]@[64,256] + b, then LN(256)+relu
        gemm_k<<<dim3(HFG/64, NN/64, GG), 256>>>(hn, HH, HG,
                                                 up_w + (size_t)l*GG*HG*HFG, HFG, (long long)HG*HFG,
                                                 up, HFF, HFG,
                                                 up_b + (size_t)l*GG*HFG, HFG, HG, 0);
        ln_k<HFG, 128, true><<<NN*GG, 128>>>(up, up, up_lg + l*HFG, up_lb + l*HFG);
        // grouped down: per group g: [N,256]@[256,64] + b, then LN(64)
        gemm_k<<<dim3(HG/64, NN/64, GG), 256>>>(up, HFF, HFG,
                                                dn_w + (size_t)l*GG*HFG*HG, HG, (long long)HFG*HG,
                                                dn, HH, HG,
                                                dn_b + (size_t)l*GG*HG, HG, HFG, 0);
        ln_k<HG, 64, false><<<NN*GG, 64>>>(dn, dn, dn_lg + l*HG, dn_lb + l*HG);
        res_k<<<NN, 128>>>(h, dn, gamma + l*HH);
    }

    pool_k<<<dim3(BB, HH/128), 128>>>(h, starts, out);
}

// round 4
// speedup vs baseline: 1.2484x; 1.2484x over previous
#include <cuda_runtime.h>
#include <cuda_bf16.h>
#include <mma.h>
#include <math.h>

using namespace nvcuda;

// Problem constants (fixed instance)
#define NN    8192
#define BB    32
#define NMAX  512
#define FF    128
#define HH    512
#define LL    3
#define GG    8
#define HFF   2048
#define EE    131072
#define HG    (HH/GG)    // 64
#define HFG   (HFF/GG)   // 256
#define ADJW  16         // 512 bits / 32
#define ADJTOT ((size_t)BB*NMAX*ADJW)

#define FLAG_ACC 1
#define FLAG_SIG 2

// GEMM tiling
#define BM 128
#define BN 64
#define BK 32
#define LDA_S 40   // BK + 8 pad
#define LDB_S 72   // BN + 8 pad
#define LDC_S 72   // BN + 8 pad

// -------------------- scratch (device globals; no allocs) --------------------
__device__ __align__(16) float    g_h  [NN*HH];
__device__ __align__(16) float    g_hg [NN*HH];
__device__ __align__(16) float    g_qk [NN*HH];
__device__ __align__(16) float    g_att[NN*HH];
__device__ __align__(16) float    g_out[NN*HH];
__device__ __align__(16) float    g_hn [NN*HH];
__device__ __align__(16) float    g_up [NN*HFF];
__device__ __align__(16) float    g_dn [NN*HH];
__device__ float    g_deg[NN];
__device__ int      g_starts[BB+1];
__device__ int      g_pos[NN];
__device__ unsigned g_adj[ADJTOT];

__device__ __forceinline__ float sigf(float x){ return 1.f/(1.f+__expf(-x)); }

// -------------------- graph structure --------------------
__global__ void clear_adj_k(unsigned* __restrict__ adj){
    size_t i = (size_t)blockIdx.x*blockDim.x + threadIdx.x;
    if (i < ADJTOT) adj[i] = 0u;
}

__global__ void starts_k(const int* __restrict__ batch, int* __restrict__ starts){
    int n = blockIdx.x*blockDim.x + threadIdx.x;
    if (n >= NN) return;
    if (n == 0){ starts[batch[0]] = 0; starts[BB] = NN; }
    else if (batch[n] != batch[n-1]) starts[batch[n]] = n;
}

__global__ void pos_self_k(const int* __restrict__ batch, const int* __restrict__ starts,
                           int* __restrict__ pos, unsigned* __restrict__ adj){
    int n = blockIdx.x*blockDim.x + threadIdx.x;
    if (n >= NN) return;
    int b = batch[n];
    int p = n - starts[b];
    pos[n] = p;
    atomicOr(&adj[((size_t)b*NMAX + p)*ADJW + (p>>5)], 1u << (p&31));
}

__global__ void edge_k(const int* __restrict__ ei, const int* __restrict__ batch,
                       const int* __restrict__ pos, unsigned* __restrict__ adj){
    int e = blockIdx.x*blockDim.x + threadIdx.x;
    if (e >= EE) return;
    int s = ei[e];
    int d = ei[EE + e];
    int b = batch[s];
    int ps = pos[s], pd = pos[d];
    atomicOr(&adj[((size_t)b*NMAX + ps)*ADJW + (pd>>5)], 1u << (pd&31));
}

__global__ void deg_k(const int* __restrict__ batch, const int* __restrict__ pos,
                      const unsigned* __restrict__ adj, float* __restrict__ deg){
    int n = blockIdx.x*blockDim.x + threadIdx.x;
    if (n >= NN) return;
    int b = batch[n];
    const unsigned* row = adj + ((size_t)b*NMAX + pos[n])*ADJW;
    int c = 0;
    #pragma unroll
    for (int w = 0; w < ADJW; w++) c += __popc(row[w]);
    deg[n] = (float)c;
}

// -------------------- TF32 tensor-core GEMM: C[=|+=] A@W (+bias) (sigmoid?) ----
// A: row-major [M,K] ld=lda, W: row-major [K,N] ld=ldw, C: row-major ld=ldc.
// Block tile 128x64, BK=32, 8 warps (each 32x32 = 2x2 wmma m16n16k8 tiles).
// grid: (N/64, M/128, groups); per-group pointer offsets via element strides.
struct SmAB { float a[BM*LDA_S]; float b[BK*LDB_S]; };
union  SmU  { SmAB ab; float c[BM*LDC_S]; };

__global__ void __launch_bounds__(256)
gemm_tc(const float* __restrict__ A, int lda, long long sAz,
        const float* __restrict__ W, int ldw, long long sWz,
        float*       __restrict__ C, int ldc, long long sCz,
        const float* __restrict__ bias, long long sBz,
        int K, int flags)
{
    A += (size_t)blockIdx.z * sAz;
    W += (size_t)blockIdx.z * sWz;
    C += (size_t)blockIdx.z * sCz;
    if (bias) bias += (size_t)blockIdx.z * sBz;

    __shared__ __align__(16) SmU sm;
    float* As = sm.ab.a;
    float* Bs = sm.ab.b;

    int tid  = threadIdx.x;
    int warp = tid >> 5;
    int wm   = warp >> 1;   // 0..3 -> 32-row group
    int wn   = warp & 1;    // 0..1 -> 32-col group
    int row0 = blockIdx.y * BM;
    int col0 = blockIdx.x * BN;

    wmma::fragment<wmma::accumulator, 16, 16, 8, float> acc[2][2];
    #pragma unroll
    for (int i = 0; i < 2; i++)
        #pragma unroll
        for (int j = 0; j < 2; j++)
            wmma::fill_fragment(acc[i][j], 0.0f);

    // A loader: 2 threads/row, 16 floats each.  B loader: 8 threads/row, 8 floats each.
    int ar  = tid >> 1,  ac0 = (tid & 1) * 16;
    int br  = tid >> 3,  bc0 = (tid & 7) * 8;

    for (int k0 = 0; k0 < K; k0 += BK){
        #pragma unroll
        for (int i = 0; i < 4; i++){
            float4 v = *(const float4*)(A + (size_t)(row0 + ar)*lda + k0 + ac0 + i*4);
            float* d = &As[ar*LDA_S + ac0 + i*4];
            d[0] = wmma::__float_to_tf32(v.x);
            d[1] = wmma::__float_to_tf32(v.y);
            d[2] = wmma::__float_to_tf32(v.z);
            d[3] = wmma::__float_to_tf32(v.w);
        }
        #pragma unroll
        for (int i = 0; i < 2; i++){
            float4 v = *(const float4*)(W + (size_t)(k0 + br)*ldw + col0 + bc0 + i*4);
            float* d = &Bs[br*LDB_S + bc0 + i*4];
            d[0] = wmma::__float_to_tf32(v.x);
            d[1] = wmma::__float_to_tf32(v.y);
            d[2] = wmma::__float_to_tf32(v.z);
            d[3] = wmma::__float_to_tf32(v.w);
        }
        __syncthreads();

        #pragma unroll
        for (int kk = 0; kk < BK; kk += 8){
            wmma::fragment<wmma::matrix_a, 16, 16, 8, wmma::precision::tf32, wmma::row_major> fa[2];
            wmma::fragment<wmma::matrix_b, 16, 16, 8, wmma::precision::tf32, wmma::row_major> fb[2];
            #pragma unroll
            for (int i = 0; i < 2; i++)
                wmma::load_matrix_sync(fa[i], &As[(wm*32 + i*16)*LDA_S + kk], LDA_S);
            #pragma unroll
            for (int j = 0; j < 2; j++)
                wmma::load_matrix_sync(fb[j], &Bs[kk*LDB_S + wn*32 + j*16], LDB_S);
            #pragma unroll
            for (int i = 0; i < 2; i++)
                #pragma unroll
                for (int j = 0; j < 2; j++)
                    wmma::mma_sync(acc[i][j], fa[i], fb[j], acc[i][j]);
        }
        __syncthreads();
    }

    // epilogue via smem (union reuses A/B staging)
    #pragma unroll
    for (int i = 0; i < 2; i++)
        #pragma unroll
        for (int j = 0; j < 2; j++)
            wmma::store_matrix_sync(&sm.c[(wm*32 + i*16)*LDC_S + wn*32 + j*16],
                                    acc[i][j], LDC_S, wmma::mem_row_major);
    __syncthreads();

    int er   = tid >> 1;            // 0..127
    int ecol = (tid & 1) * 32;      // 0 or 32
    #pragma unroll
    for (int i = 0; i < 8; i++){
        int cc = ecol + i*4;
        float4 v = *(const float4*)&sm.c[er*LDC_S + cc];
        size_t gr = (size_t)(row0 + er)*ldc + col0 + cc;
        if (bias){
            v.x += bias[col0+cc+0]; v.y += bias[col0+cc+1];
            v.z += bias[col0+cc+2]; v.w += bias[col0+cc+3];
        }
        if (flags & FLAG_ACC){
            float4 c0 = *(const float4*)(C + gr);
            v.x += c0.x; v.y += c0.y; v.z += c0.z; v.w += c0.w;
        }
        if (flags & FLAG_SIG){
            v.x = sigf(v.x); v.y = sigf(v.y); v.z = sigf(v.z); v.w = sigf(v.w);
        }
        *(float4*)(C + gr) = v;
    }
}

// -------------------- elementwise / reductions --------------------
__global__ void gate_k(const float* __restrict__ h, const float* __restrict__ deg,
                       const float* __restrict__ Wd, const float* __restrict__ bd,
                       float* __restrict__ hg){
    int n = blockIdx.x, t = threadIdx.x;  // 128 threads, float4 each
    float d = deg[n];
    float4 hv = ((const float4*)(h + (size_t)n*HH))[t];
    float4 wv = ((const float4*)Wd)[t];
    float4 bv = ((const float4*)bd)[t];
    float4 o;
    o.x = hv.x * sigf(d*wv.x + bv.x);
    o.y = hv.y * sigf(d*wv.y + bv.y);
    o.z = hv.z * sigf(d*wv.z + bv.z);
    o.w = hv.w * sigf(d*wv.w + bv.w);
    ((float4*)(hg + (size_t)n*HH))[t] = o;
}

// sparse masked attention: warp per node
__global__ void attn_k(const float* __restrict__ qk, const float* __restrict__ hg,
                       const unsigned* __restrict__ adj, const int* __restrict__ starts,
                       const int* __restrict__ batch, float* __restrict__ out){
    int warp = (blockIdx.x*blockDim.x + threadIdx.x) >> 5;
    int lane = threadIdx.x & 31;
    if (warp >= NN) return;
    int n = warp;
    int b = batch[n];
    int start = starts[b];
    int p = n - start;
    const unsigned* row = adj + ((size_t)b*NMAX + p)*ADJW;
    const float4* qn4 = (const float4*)(qk + (size_t)n*HH);
    float4 qn[4];
    #pragma unroll
    for (int c = 0; c < 4; c++) qn[c] = qn4[lane + c*32];
    float4 acc[4] = {{0,0,0,0},{0,0,0,0},{0,0,0,0},{0,0,0,0}};
    float rowsum = 0.f;
    const float inv_sqrt_h = 0.044194173824159216f; // 1/sqrt(512)

    for (int w = 0; w < ADJW; w++){
        unsigned bits = row[w];
        while (bits){
            int t = __ffs((int)bits) - 1; bits &= bits - 1;
            int m = start + w*32 + t;
            const float4* qm4 = (const float4*)(qk + (size_t)m*HH);
            float s = 0.f;
            #pragma unroll
            for (int c = 0; c < 4; c++){
                float4 v = qm4[lane + c*32];
                s += qn[c].x*v.x + qn[c].y*v.y + qn[c].z*v.z + qn[c].w*v.w;
            }
            #pragma unroll
            for (int o = 16; o; o >>= 1) s += __shfl_xor_sync(0xffffffffu, s, o);
            s *= inv_sqrt_h;
            rowsum += s;
            const float4* hm4 = (const float4*)(hg + (size_t)m*HH);
            #pragma unroll
            for (int c = 0; c < 4; c++){
                float4 hv = hm4[lane + c*32];
                acc[c].x += s*hv.x; acc[c].y += s*hv.y;
                acc[c].z += s*hv.z; acc[c].w += s*hv.w;
            }
        }
    }
    float inv = 1.f/(rowsum + 1e-6f);
    float4* o4 = (float4*)(out + (size_t)n*HH);
    #pragma unroll
    for (int c = 0; c < 4; c++){
        acc[c].x *= inv; acc[c].y *= inv; acc[c].z *= inv; acc[c].w *= inv;
        o4[lane + c*32] = acc[c];
    }
}

// l2-normalize rows then relu
__global__ void l2relu_k(const float* __restrict__ x, float* __restrict__ y){
    int n = blockIdx.x, t = threadIdx.x; // 128 threads, float4 each
    float4 v = ((const float4*)(x + (size_t)n*HH))[t];
    float ss = v.x*v.x + v.y*v.y + v.z*v.z + v.w*v.w;
    #pragma unroll
    for (int o = 16; o; o >>= 1) ss += __shfl_xor_sync(0xffffffffu, ss, o);
    __shared__ float sh[4];
    __shared__ float sinv;
    int w = t >> 5, l = t & 31;
    if (l == 0) sh[w] = ss;
    __syncthreads();
    if (t == 0){
        float tot = sh[0] + sh[1] + sh[2] + sh[3];
        sinv = 1.f / fmaxf(sqrtf(tot), 1e-12f);
    }
    __syncthreads();
    float iv = sinv;
    float4 o;
    o.x = fmaxf(v.x*iv, 0.f); o.y = fmaxf(v.y*iv, 0.f);
    o.z = fmaxf(v.z*iv, 0.f); o.w = fmaxf(v.w*iv, 0.f);
    ((float4*)(y + (size_t)n*HH))[t] = o;
}

// layernorm over width W, NT threads/row; optional fused relu; in-place safe
template<int W, int NT, bool RELU>
__global__ void ln_k(const float* __restrict__ x, float* __restrict__ y,
                     const float* __restrict__ g, const float* __restrict__ b){
    constexpr int PT = W / NT;
    int row = blockIdx.x, t = threadIdx.x;
    const float* xr = x + (size_t)row*W;
    float*       yr = y + (size_t)row*W;
    float v[PT]; float s = 0.f, s2 = 0.f;
    #pragma unroll
    for (int i = 0; i < PT; i++){ float u = xr[t + i*NT]; v[i] = u; s += u; s2 += u*u; }
    #pragma unroll
    for (int o = 16; o; o >>= 1){
        s  += __shfl_xor_sync(0xffffffffu, s,  o);
        s2 += __shfl_xor_sync(0xffffffffu, s2, o);
    }
    __shared__ float sh[2][NT/32];
    __shared__ float mb[2];
    int w = t >> 5, l = t & 31;
    if (l == 0){ sh[0][w] = s; sh[1][w] = s2; }
    __syncthreads();
    if (t == 0){
        float ts = 0.f, ts2 = 0.f;
        #pragma unroll
        for (int i = 0; i < NT/32; i++){ ts += sh[0][i]; ts2 += sh[1][i]; }
        float mean = ts / W;
        float var  = ts2 / W - mean*mean;
        mb[0] = mean; mb[1] = rsqrtf(var + 1e-5f);
    }
    __syncthreads();
    float mean = mb[0], rstd = mb[1];
    #pragma unroll
    for (int i = 0; i < PT; i++){
        int c = t + i*NT;
        float o = (v[i] - mean) * rstd * g[c] + b[c];
        if (RELU) o = fmaxf(o, 0.f);
        yr[c] = o;
    }
}

__global__ void res_k(float* __restrict__ h, const float* __restrict__ dn,
                      const float* __restrict__ gamma){
    int n = blockIdx.x, t = threadIdx.x;
    float4 hv = ((const float4*)(h + (size_t)n*HH))[t];
    float4 dv = ((const float4*)(dn + (size_t)n*HH))[t];
    float4 gm = ((const float4*)gamma)[t];
    hv.x += gm.x*dv.x; hv.y += gm.y*dv.y; hv.z += gm.z*dv.z; hv.w += gm.w*dv.w;
    ((float4*)(h + (size_t)n*HH))[t] = hv;
}

__global__ void pool_k(const float* __restrict__ h, const int* __restrict__ starts,
                       float* __restrict__ out){
    int b = blockIdx.x;
    int f = blockIdx.y*128 + threadIdx.x;
    int s = starts[b], e = starts[b+1];
    float acc = 0.f;
    for (int n = s; n < e; n++) acc += h[(size_t)n*HH + f];
    out[(size_t)b*HH + f] = acc;
}

// -------------------- launcher --------------------
extern "C" void kernel_launch(void* const* d_in, const int* in_sizes, int n_in,
                              void* d_out, int out_size){
    const float* x     = (const float*)d_in[0];
    const int*   ei    = (const int*)d_in[1];     // int32 per harness dtype contract
    const int*   batch = (const int*)d_in[2];     // int32 per harness dtype contract
    const float* W_in = (const float*)d_in[3];
    const float* b_in = (const float*)d_in[4];
    const float* Wqk  = (const float*)d_in[5];
    const float* bqk  = (const float*)d_in[6];
    const float* Wd   = (const float*)d_in[7];
    const float* bd   = (const float*)d_in[8];
    const float* Wl   = (const float*)d_in[9];
    const float* bl   = (const float*)d_in[10];
    const float* Wr   = (const float*)d_in[11];
    const float* gamma= (const float*)d_in[12];
    const float* ln_g = (const float*)d_in[13];
    const float* ln_b = (const float*)d_in[14];
    const float* up_w = (const float*)d_in[15];
    const float* up_b = (const float*)d_in[16];
    const float* up_lg= (const float*)d_in[17];
    const float* up_lb= (const float*)d_in[18];
    const float* dn_w = (const float*)d_in[19];
    const float* dn_b = (const float*)d_in[20];
    const float* dn_lg= (const float*)d_in[21];
    const float* dn_lb= (const float*)d_in[22];
    float* out = (float*)d_out;

    float *h, *hg, *qk, *att, *ob, *hn, *up, *dn, *deg;
    int *starts, *pos; unsigned* adj;
    cudaGetSymbolAddress((void**)&h,   g_h);
    cudaGetSymbolAddress((void**)&hg,  g_hg);
    cudaGetSymbolAddress((void**)&qk,  g_qk);
    cudaGetSymbolAddress((void**)&att, g_att);
    cudaGetSymbolAddress((void**)&ob,  g_out);
    cudaGetSymbolAddress((void**)&hn,  g_hn);
    cudaGetSymbolAddress((void**)&up,  g_up);
    cudaGetSymbolAddress((void**)&dn,  g_dn);
    cudaGetSymbolAddress((void**)&deg, g_deg);
    cudaGetSymbolAddress((void**)&starts, g_starts);
    cudaGetSymbolAddress((void**)&pos,    g_pos);
    cudaGetSymbolAddress((void**)&adj,    g_adj);

    // graph structure (clear kernel: memset nodes can't target __device__ symbols)
    clear_adj_k<<<(int)((ADJTOT + 255)/256), 256>>>(adj);
    starts_k  <<<NN/256, 256>>>(batch, starts);
    pos_self_k<<<NN/256, 256>>>(batch, starts, pos, adj);
    edge_k    <<<EE/256, 256>>>(ei, batch, pos, adj);
    deg_k     <<<NN/256, 256>>>(batch, pos, adj, deg);

    // h = x @ W_in + b_in
    gemm_tc<<<dim3(HH/BN, NN/BM, 1), 256>>>(x, FF, 0, W_in, HH, 0, h, HH, 0, b_in, 0, FF, 0);

    for (int l = 0; l < LL; l++){
        gate_k<<<NN, 128>>>(h, deg, Wd + l*HH, bd + l*HH, hg);
        gemm_tc<<<dim3(HH/BN, NN/BM, 1), 256>>>(hg, HH, 0, Wqk + (size_t)l*HH*HH, HH, 0,
                                                qk, HH, 0, bqk + l*HH, 0, HH, FLAG_SIG);
        attn_k<<<NN/8, 256>>>(qk, hg, adj, starts, batch, att);
        gemm_tc<<<dim3(HH/BN, NN/BM, 1), 256>>>(att, HH, 0, Wl + (size_t)l*HH*HH, HH, 0,
                                                ob, HH, 0, bl + l*HH, 0, HH, 0);
        gemm_tc<<<dim3(HH/BN, NN/BM, 1), 256>>>(hg, HH, 0, Wr + (size_t)l*HH*HH, HH, 0,
                                                ob, HH, 0, nullptr, 0, HH, FLAG_ACC);
        l2relu_k<<<NN, 128>>>(ob, h);
        ln_k<HH, 128, false><<<NN, 128>>>(h, hn, ln_g + l*HH, ln_b + l*HH);
        // grouped up: per group g: [N,64]@[64,256] + b, then LN(256)+relu
        gemm_tc<<<dim3(HFG/BN, NN/BM, GG), 256>>>(hn, HH, HG,
                                                  up_w + (size_t)l*GG*HG*HFG, HFG, (long long)HG*HFG,
                                                  up, HFF, HFG,
                                                  up_b + (size_t)l*GG*HFG, HFG, HG, 0);
        ln_k<HFG, 128, true><<<NN*GG, 128>>>(up, up, up_lg + l*HFG, up_lb + l*HFG);
        // grouped down: per group g: [N,256]@[256,64] + b, then LN(64)
        gemm_tc<<<dim3(HG/BN, NN/BM, GG), 256>>>(up, HFF, HFG,
                                                 dn_w + (size_t)l*GG*HFG*HG, HG, (long long)HFG*HG,
                                                 dn, HH, HG,
                                                 dn_b + (size_t)l*GG*HG, HG, HFG, 0);
        ln_k<HG, 64, false><<<NN*GG, 64>>>(dn, dn, dn_lg + l*HG, dn_lb + l*HG);
        res_k<<<NN, 128>>>(h, dn, gamma + l*HH);
    }

    pool_k<<<dim3(BB, HH/128), 128>>>(h, starts, out);
}

// round 5
// speedup vs baseline: 1.3267x; 1.0627x over previous
#include <cuda_runtime.h>
#include <cuda_bf16.h>
#include <mma.h>
#include <math.h>

using namespace nvcuda;

// Problem constants (fixed instance)
#define NN    8192
#define BB    32
#define NMAX  512
#define FF    128
#define HH    512
#define LL    3
#define GG    8
#define HFF   2048
#define EE    131072
#define HG    (HH/GG)    // 64
#define HFG   (HFF/GG)   // 256
#define ADJW  16         // 512 bits / 32
#define ADJTOT ((size_t)BB*NMAX*ADJW)

#define FLAG_ACC 1
#define FLAG_SIG 2

// GEMM tiling
#define BM 128
#define BN 64
#define BK 32
#define LDA_S 40   // BK + 8 pad
#define LDB_S 72   // BN + 8 pad
#define LDC_S 72   // BN + 8 pad
#define ASZ (BM*LDA_S)            // floats per A stage (5120)
#define BSZ (BK*LDB_S)            // floats per B stage (2304)
#define GEMM_SMEM (2*(ASZ+BSZ)*sizeof(float))   // 59392 bytes

// -------------------- scratch (device globals; no allocs) --------------------
__device__ __align__(16) float    g_h  [NN*HH];
__device__ __align__(16) float    g_hg [NN*HH];
__device__ __align__(16) float    g_qk [NN*HH];
__device__ __align__(16) float    g_att[NN*HH];
__device__ __align__(16) float    g_out[NN*HH];
__device__ __align__(16) float    g_hn [NN*HH];
__device__ __align__(16) float    g_up [NN*HFF];
__device__ __align__(16) float    g_dn [NN*HH];
__device__ float    g_deg[NN];
__device__ int      g_starts[BB+1];
__device__ int      g_pos[NN];
__device__ unsigned g_adj[ADJTOT];

__device__ __forceinline__ float sigf(float x){ return 1.f/(1.f+__expf(-x)); }

__device__ __forceinline__ void cpa16(float* s, const float* g){
    unsigned a = (unsigned)__cvta_generic_to_shared(s);
    asm volatile("cp.async.cg.shared.global [%0], [%1], 16;" :: "r"(a), "l"(g));
}
__device__ __forceinline__ void cpa_commit(){ asm volatile("cp.async.commit_group;"); }
template<int N> __device__ __forceinline__ void cpa_wait(){
    asm volatile("cp.async.wait_group %0;" :: "n"(N));
}

// -------------------- graph structure --------------------
__global__ void clear_adj_k(unsigned* __restrict__ adj){
    size_t i = (size_t)blockIdx.x*blockDim.x + threadIdx.x;
    if (i < ADJTOT) adj[i] = 0u;
}

__global__ void starts_k(const int* __restrict__ batch, int* __restrict__ starts){
    int n = blockIdx.x*blockDim.x + threadIdx.x;
    if (n >= NN) return;
    if (n == 0){ starts[batch[0]] = 0; starts[BB] = NN; }
    else if (batch[n] != batch[n-1]) starts[batch[n]] = n;
}

__global__ void pos_self_k(const int* __restrict__ batch, const int* __restrict__ starts,
                           int* __restrict__ pos, unsigned* __restrict__ adj){
    int n = blockIdx.x*blockDim.x + threadIdx.x;
    if (n >= NN) return;
    int b = batch[n];
    int p = n - starts[b];
    pos[n] = p;
    atomicOr(&adj[((size_t)b*NMAX + p)*ADJW + (p>>5)], 1u << (p&31));
}

__global__ void edge_k(const int* __restrict__ ei, const int* __restrict__ batch,
                       const int* __restrict__ pos, unsigned* __restrict__ adj){
    int e = blockIdx.x*blockDim.x + threadIdx.x;
    if (e >= EE) return;
    int s = ei[e];
    int d = ei[EE + e];
    int b = batch[s];
    int ps = pos[s], pd = pos[d];
    atomicOr(&adj[((size_t)b*NMAX + ps)*ADJW + (pd>>5)], 1u << (pd&31));
}

__global__ void deg_k(const int* __restrict__ batch, const int* __restrict__ pos,
                      const unsigned* __restrict__ adj, float* __restrict__ deg){
    int n = blockIdx.x*blockDim.x + threadIdx.x;
    if (n >= NN) return;
    int b = batch[n];
    const unsigned* row = adj + ((size_t)b*NMAX + pos[n])*ADJW;
    int c = 0;
    #pragma unroll
    for (int w = 0; w < ADJW; w++) c += __popc(row[w]);
    deg[n] = (float)c;
}

// -------------------- TF32 tensor-core GEMM, cp.async double-buffered --------
// C = A@W (+ A2@W2 if DUAL) (+bias) (sigmoid?).  Row-major everywhere.
// Block tile 128x64, BK=32, 2-stage cp.async pipeline, 8 warps (2x2 wmma each).
// grid: (N/64, M/128, groups); per-group pointer offsets via element strides.
template<bool DUAL>
__global__ void __launch_bounds__(256)
gemm_tc(const float* __restrict__ A, int lda, long long sAz,
        const float* __restrict__ W, int ldw, long long sWz,
        const float* __restrict__ A2, const float* __restrict__ W2,
        float*       __restrict__ C, int ldc, long long sCz,
        const float* __restrict__ bias, long long sBz,
        int K, int flags)
{
    A += (size_t)blockIdx.z * sAz;
    W += (size_t)blockIdx.z * sWz;
    C += (size_t)blockIdx.z * sCz;
    if (bias) bias += (size_t)blockIdx.z * sBz;

    extern __shared__ __align__(16) float sm[];

    int tid  = threadIdx.x;
    int warp = tid >> 5;
    int wm   = warp >> 1;   // 0..3 -> 32-row group
    int wn   = warp & 1;    // 0..1 -> 32-col group
    int row0 = blockIdx.y * BM;
    int col0 = blockIdx.x * BN;

    // loaders: A 2 thr/row x 16 floats; B 8 thr/row x 8 floats
    int ar  = tid >> 1,  ac0 = (tid & 1) * 16;
    int br  = tid >> 3,  bc0 = (tid & 7) * 8;

    wmma::fragment<wmma::accumulator, 16, 16, 8, float> acc[2][2];
    #pragma unroll
    for (int i = 0; i < 2; i++)
        #pragma unroll
        for (int j = 0; j < 2; j++)
            wmma::fill_fragment(acc[i][j], 0.0f);

    const int T = K / BK;

    #pragma unroll
    for (int phase = 0; phase < (DUAL ? 2 : 1); phase++){
        const float* Ap = (DUAL && phase) ? A2 : A;
        const float* Wp = (DUAL && phase) ? W2 : W;

        // prefetch tile 0 into stage 0
        {
            float* As = sm;               // stage 0
            float* Bs = sm + ASZ;
            const float* ag = Ap + (size_t)(row0 + ar)*lda + ac0;
            #pragma unroll
            for (int i = 0; i < 4; i++) cpa16(&As[ar*LDA_S + ac0 + i*4], ag + i*4);
            const float* bg = Wp + (size_t)br*ldw + col0 + bc0;
            #pragma unroll
            for (int i = 0; i < 2; i++) cpa16(&Bs[br*LDB_S + bc0 + i*4], bg + i*4);
            cpa_commit();
        }

        for (int it = 0; it < T; it++){
            int cur = it & 1;
            if (it + 1 < T){
                int nxt = cur ^ 1;
                float* As = sm + nxt*(ASZ+BSZ);
                float* Bs = As + ASZ;
                int k0 = (it + 1) * BK;
                const float* ag = Ap + (size_t)(row0 + ar)*lda + k0 + ac0;
                #pragma unroll
                for (int i = 0; i < 4; i++) cpa16(&As[ar*LDA_S + ac0 + i*4], ag + i*4);
                const float* bg = Wp + (size_t)(k0 + br)*ldw + col0 + bc0;
                #pragma unroll
                for (int i = 0; i < 2; i++) cpa16(&Bs[br*LDB_S + bc0 + i*4], bg + i*4);
                cpa_commit();
                cpa_wait<1>();
            } else {
                cpa_wait<0>();
            }
            __syncthreads();

            float* As = sm + cur*(ASZ+BSZ);
            float* Bs = As + ASZ;
            #pragma unroll
            for (int kk = 0; kk < BK; kk += 8){
                wmma::fragment<wmma::matrix_a, 16, 16, 8, wmma::precision::tf32, wmma::row_major> fa[2];
                wmma::fragment<wmma::matrix_b, 16, 16, 8, wmma::precision::tf32, wmma::row_major> fb[2];
                #pragma unroll
                for (int i = 0; i < 2; i++){
                    wmma::load_matrix_sync(fa[i], &As[(wm*32 + i*16)*LDA_S + kk], LDA_S);
                    #pragma unroll
                    for (int t = 0; t < fa[i].num_elements; t++)
                        fa[i].x[t] = wmma::__float_to_tf32(fa[i].x[t]);
                }
                #pragma unroll
                for (int j = 0; j < 2; j++){
                    wmma::load_matrix_sync(fb[j], &Bs[kk*LDB_S + wn*32 + j*16], LDB_S);
                    #pragma unroll
                    for (int t = 0; t < fb[j].num_elements; t++)
                        fb[j].x[t] = wmma::__float_to_tf32(fb[j].x[t]);
                }
                #pragma unroll
                for (int i = 0; i < 2; i++)
                    #pragma unroll
                    for (int j = 0; j < 2; j++)
                        wmma::mma_sync(acc[i][j], fa[i], fb[j], acc[i][j]);
            }
            __syncthreads();
        }
    }

    // epilogue via smem (reuses pipeline staging)
    #pragma unroll
    for (int i = 0; i < 2; i++)
        #pragma unroll
        for (int j = 0; j < 2; j++)
            wmma::store_matrix_sync(&sm[(wm*32 + i*16)*LDC_S + wn*32 + j*16],
                                    acc[i][j], LDC_S, wmma::mem_row_major);
    __syncthreads();

    int er   = tid >> 1;            // 0..127
    int ecol = (tid & 1) * 32;      // 0 or 32
    #pragma unroll
    for (int i = 0; i < 8; i++){
        int cc = ecol + i*4;
        float4 v = *(const float4*)&sm[er*LDC_S + cc];
        size_t gr = (size_t)(row0 + er)*ldc + col0 + cc;
        if (bias){
            v.x += bias[col0+cc+0]; v.y += bias[col0+cc+1];
            v.z += bias[col0+cc+2]; v.w += bias[col0+cc+3];
        }
        if (flags & FLAG_ACC){
            float4 c0 = *(const float4*)(C + gr);
            v.x += c0.x; v.y += c0.y; v.z += c0.z; v.w += c0.w;
        }
        if (flags & FLAG_SIG){
            v.x = sigf(v.x); v.y = sigf(v.y); v.z = sigf(v.z); v.w = sigf(v.w);
        }
        *(float4*)(C + gr) = v;
    }
}

// -------------------- elementwise / reductions --------------------
__global__ void gate_k(const float* __restrict__ h, const float* __restrict__ deg,
                       const float* __restrict__ Wd, const float* __restrict__ bd,
                       float* __restrict__ hg){
    int n = blockIdx.x, t = threadIdx.x;  // 128 threads, float4 each
    float d = deg[n];
    float4 hv = ((const float4*)(h + (size_t)n*HH))[t];
    float4 wv = ((const float4*)Wd)[t];
    float4 bv = ((const float4*)bd)[t];
    float4 o;
    o.x = hv.x * sigf(d*wv.x + bv.x);
    o.y = hv.y * sigf(d*wv.y + bv.y);
    o.z = hv.z * sigf(d*wv.z + bv.z);
    o.w = hv.w * sigf(d*wv.w + bv.w);
    ((float4*)(hg + (size_t)n*HH))[t] = o;
}

// sparse masked attention: warp per node
__global__ void attn_k(const float* __restrict__ qk, const float* __restrict__ hg,
                       const unsigned* __restrict__ adj, const int* __restrict__ starts,
                       const int* __restrict__ batch, float* __restrict__ out){
    int warp = (blockIdx.x*blockDim.x + threadIdx.x) >> 5;
    int lane = threadIdx.x & 31;
    if (warp >= NN) return;
    int n = warp;
    int b = batch[n];
    int start = starts[b];
    int p = n - start;
    const unsigned* row = adj + ((size_t)b*NMAX + p)*ADJW;
    const float4* qn4 = (const float4*)(qk + (size_t)n*HH);
    float4 qn[4];
    #pragma unroll
    for (int c = 0; c < 4; c++) qn[c] = qn4[lane + c*32];
    float4 acc[4] = {{0,0,0,0},{0,0,0,0},{0,0,0,0},{0,0,0,0}};
    float rowsum = 0.f;
    const float inv_sqrt_h = 0.044194173824159216f; // 1/sqrt(512)

    for (int w = 0; w < ADJW; w++){
        unsigned bits = row[w];
        while (bits){
            int t = __ffs((int)bits) - 1; bits &= bits - 1;
            int m = start + w*32 + t;
            const float4* qm4 = (const float4*)(qk + (size_t)m*HH);
            float s = 0.f;
            #pragma unroll
            for (int c = 0; c < 4; c++){
                float4 v = qm4[lane + c*32];
                s += qn[c].x*v.x + qn[c].y*v.y + qn[c].z*v.z + qn[c].w*v.w;
            }
            #pragma unroll
            for (int o = 16; o; o >>= 1) s += __shfl_xor_sync(0xffffffffu, s, o);
            s *= inv_sqrt_h;
            rowsum += s;
            const float4* hm4 = (const float4*)(hg + (size_t)m*HH);
            #pragma unroll
            for (int c = 0; c < 4; c++){
                float4 hv = hm4[lane + c*32];
                acc[c].x += s*hv.x; acc[c].y += s*hv.y;
                acc[c].z += s*hv.z; acc[c].w += s*hv.w;
            }
        }
    }
    float inv = 1.f/(rowsum + 1e-6f);
    float4* o4 = (float4*)(out + (size_t)n*HH);
    #pragma unroll
    for (int c = 0; c < 4; c++){
        acc[c].x *= inv; acc[c].y *= inv; acc[c].z *= inv; acc[c].w *= inv;
        o4[lane + c*32] = acc[c];
    }
}

// l2-normalize rows then relu
__global__ void l2relu_k(const float* __restrict__ x, float* __restrict__ y){
    int n = blockIdx.x, t = threadIdx.x; // 128 threads, float4 each
    float4 v = ((const float4*)(x + (size_t)n*HH))[t];
    float ss = v.x*v.x + v.y*v.y + v.z*v.z + v.w*v.w;
    #pragma unroll
    for (int o = 16; o; o >>= 1) ss += __shfl_xor_sync(0xffffffffu, ss, o);
    __shared__ float sh[4];
    __shared__ float sinv;
    int w = t >> 5, l = t & 31;
    if (l == 0) sh[w] = ss;
    __syncthreads();
    if (t == 0){
        float tot = sh[0] + sh[1] + sh[2] + sh[3];
        sinv = 1.f / fmaxf(sqrtf(tot), 1e-12f);
    }
    __syncthreads();
    float iv = sinv;
    float4 o;
    o.x = fmaxf(v.x*iv, 0.f); o.y = fmaxf(v.y*iv, 0.f);
    o.z = fmaxf(v.z*iv, 0.f); o.w = fmaxf(v.w*iv, 0.f);
    ((float4*)(y + (size_t)n*HH))[t] = o;
}

// layernorm over width W, NT threads/row; optional fused relu; in-place safe
template<int W, int NT, bool RELU>
__global__ void ln_k(const float* __restrict__ x, float* __restrict__ y,
                     const float* __restrict__ g, const float* __restrict__ b){
    constexpr int PT = W / NT;
    int row = blockIdx.x, t = threadIdx.x;
    const float* xr = x + (size_t)row*W;
    float*       yr = y + (size_t)row*W;
    float v[PT]; float s = 0.f, s2 = 0.f;
    #pragma unroll
    for (int i = 0; i < PT; i++){ float u = xr[t + i*NT]; v[i] = u; s += u; s2 += u*u; }
    #pragma unroll
    for (int o = 16; o; o >>= 1){
        s  += __shfl_xor_sync(0xffffffffu, s,  o);
        s2 += __shfl_xor_sync(0xffffffffu, s2, o);
    }
    __shared__ float sh[2][NT/32];
    __shared__ float mb[2];
    int w = t >> 5, l = t & 31;
    if (l == 0){ sh[0][w] = s; sh[1][w] = s2; }
    __syncthreads();
    if (t == 0){
        float ts = 0.f, ts2 = 0.f;
        #pragma unroll
        for (int i = 0; i < NT/32; i++){ ts += sh[0][i]; ts2 += sh[1][i]; }
        float mean = ts / W;
        float var  = ts2 / W - mean*mean;
        mb[0] = mean; mb[1] = rsqrtf(var + 1e-5f);
    }
    __syncthreads();
    float mean = mb[0], rstd = mb[1];
    #pragma unroll
    for (int i = 0; i < PT; i++){
        int c = t + i*NT;
        float o = (v[i] - mean) * rstd * g[c] + b[c];
        if (RELU) o = fmaxf(o, 0.f);
        yr[c] = o;
    }
}

__global__ void res_k(float* __restrict__ h, const float* __restrict__ dn,
                      const float* __restrict__ gamma){
    int n = blockIdx.x, t = threadIdx.x;
    float4 hv = ((const float4*)(h + (size_t)n*HH))[t];
    float4 dv = ((const float4*)(dn + (size_t)n*HH))[t];
    float4 gm = ((const float4*)gamma)[t];
    hv.x += gm.x*dv.x; hv.y += gm.y*dv.y; hv.z += gm.z*dv.z; hv.w += gm.w*dv.w;
    ((float4*)(h + (size_t)n*HH))[t] = hv;
}

__global__ void pool_k(const float* __restrict__ h, const int* __restrict__ starts,
                       float* __restrict__ out){
    int b = blockIdx.x;
    int f = blockIdx.y*128 + threadIdx.x;
    int s = starts[b], e = starts[b+1];
    float acc = 0.f;
    for (int n = s; n < e; n++) acc += h[(size_t)n*HH + f];
    out[(size_t)b*HH + f] = acc;
}

// -------------------- launcher --------------------
extern "C" void kernel_launch(void* const* d_in, const int* in_sizes, int n_in,
                              void* d_out, int out_size){
    const float* x     = (const float*)d_in[0];
    const int*   ei    = (const int*)d_in[1];     // int32 per harness dtype contract
    const int*   batch = (const int*)d_in[2];     // int32 per harness dtype contract
    const float* W_in = (const float*)d_in[3];
    const float* b_in = (const float*)d_in[4];
    const float* Wqk  = (const float*)d_in[5];
    const float* bqk  = (const float*)d_in[6];
    const float* Wd   = (const float*)d_in[7];
    const float* bd   = (const float*)d_in[8];
    const float* Wl   = (const float*)d_in[9];
    const float* bl   = (const float*)d_in[10];
    const float* Wr   = (const float*)d_in[11];
    const float* gamma= (const float*)d_in[12];
    const float* ln_g = (const float*)d_in[13];
    const float* ln_b = (const float*)d_in[14];
    const float* up_w = (const float*)d_in[15];
    const float* up_b = (const float*)d_in[16];
    const float* up_lg= (const float*)d_in[17];
    const float* up_lb= (const float*)d_in[18];
    const float* dn_w = (const float*)d_in[19];
    const float* dn_b = (const float*)d_in[20];
    const float* dn_lg= (const float*)d_in[21];
    const float* dn_lb= (const float*)d_in[22];
    float* out = (float*)d_out;

    float *h, *hg, *qk, *att, *ob, *hn, *up, *dn, *deg;
    int *starts, *pos; unsigned* adj;
    cudaGetSymbolAddress((void**)&h,   g_h);
    cudaGetSymbolAddress((void**)&hg,  g_hg);
    cudaGetSymbolAddress((void**)&qk,  g_qk);
    cudaGetSymbolAddress((void**)&att, g_att);
    cudaGetSymbolAddress((void**)&ob,  g_out);
    cudaGetSymbolAddress((void**)&hn,  g_hn);
    cudaGetSymbolAddress((void**)&up,  g_up);
    cudaGetSymbolAddress((void**)&dn,  g_dn);
    cudaGetSymbolAddress((void**)&deg, g_deg);
    cudaGetSymbolAddress((void**)&starts, g_starts);
    cudaGetSymbolAddress((void**)&pos,    g_pos);
    cudaGetSymbolAddress((void**)&adj,    g_adj);

    // opt-in to >48KB dynamic smem (idempotent; not a stream op -> capture-safe)
    cudaFuncSetAttribute((const void*)gemm_tc<false>,
                         cudaFuncAttributeMaxDynamicSharedMemorySize, (int)GEMM_SMEM);
    cudaFuncSetAttribute((const void*)gemm_tc<true>,
                         cudaFuncAttributeMaxDynamicSharedMemorySize, (int)GEMM_SMEM);

    // graph structure (clear kernel: memset nodes can't target __device__ symbols)
    clear_adj_k<<<(int)((ADJTOT + 255)/256), 256>>>(adj);
    starts_k  <<<NN/256, 256>>>(batch, starts);
    pos_self_k<<<NN/256, 256>>>(batch, starts, pos, adj);
    edge_k    <<<EE/256, 256>>>(ei, batch, pos, adj);
    deg_k     <<<NN/256, 256>>>(batch, pos, adj, deg);

    // h = x @ W_in + b_in
    gemm_tc<false><<<dim3(HH/BN, NN/BM, 1), 256, GEMM_SMEM>>>(
        x, FF, 0, W_in, HH, 0, nullptr, nullptr, h, HH, 0, b_in, 0, FF, 0);

    for (int l = 0; l < LL; l++){
        gate_k<<<NN, 128>>>(h, deg, Wd + l*HH, bd + l*HH, hg);
        gemm_tc<false><<<dim3(HH/BN, NN/BM, 1), 256, GEMM_SMEM>>>(
            hg, HH, 0, Wqk + (size_t)l*HH*HH, HH, 0, nullptr, nullptr,
            qk, HH, 0, bqk + l*HH, 0, HH, FLAG_SIG);
        attn_k<<<NN/8, 256>>>(qk, hg, adj, starts, batch, att);
        // ob = att@Wl + hg@Wr + bl  (fused dual GEMM)
        gemm_tc<true><<<dim3(HH/BN, NN/BM, 1), 256, GEMM_SMEM>>>(
            att, HH, 0, Wl + (size_t)l*HH*HH, HH, 0,
            hg, Wr + (size_t)l*HH*HH,
            ob, HH, 0, bl + l*HH, 0, HH, 0);
        l2relu_k<<<NN, 128>>>(ob, h);
        ln_k<HH, 128, false><<<NN, 128>>>(h, hn, ln_g + l*HH, ln_b + l*HH);
        // grouped up: per group g: [N,64]@[64,256] + b, then LN(256)+relu
        gemm_tc<false><<<dim3(HFG/BN, NN/BM, GG), 256, GEMM_SMEM>>>(
            hn, HH, HG,
            up_w + (size_t)l*GG*HG*HFG, HFG, (long long)HG*HFG, nullptr, nullptr,
            up, HFF, HFG,
            up_b + (size_t)l*GG*HFG, HFG, HG, 0);
        ln_k<HFG, 128, true><<<NN*GG, 128>>>(up, up, up_lg + l*HFG, up_lb + l*HFG);
        // grouped down: per group g: [N,256]@[256,64] + b, then LN(64)
        gemm_tc<false><<<dim3(HG/BN, NN/BM, GG), 256, GEMM_SMEM>>>(
            up, HFF, HFG,
            dn_w + (size_t)l*GG*HFG*HG, HG, (long long)HFG*HG, nullptr, nullptr,
            dn, HH, HG,
            dn_b + (size_t)l*GG*HG, HG, HFG, 0);
        ln_k<HG, 64, false><<<NN*GG, 64>>>(dn, dn, dn_lg + l*HG, dn_lb + l*HG);
        res_k<<<NN, 128>>>(h, dn, gamma + l*HH);
    }

    pool_k<<<dim3(BB, HH/128), 128>>>(h, starts, out);
}

// round 6
// speedup vs baseline: 1.3968x; 1.0529x over previous
#include <cuda_runtime.h>
#include <cuda_bf16.h>
#include <mma.h>
#include <math.h>

using namespace nvcuda;

// Problem constants (fixed instance)
#define NN    8192
#define BB    32
#define NMAX  512
#define FF    128
#define HH    512
#define LL    3
#define GG    8
#define HFF   2048
#define EE    131072
#define HG    (HH/GG)    // 64
#define HFG   (HFF/GG)   // 256
#define ADJW  16         // 512 bits / 32
#define ADJTOT ((size_t)BB*NMAX*ADJW)

#define FLAG_ACC 1
#define FLAG_SIG 2

// GEMM tiling: BM=128, BK=32, BN templated (128 main / 64 small)
#define BM 128
#define BK 32
#define LDA_S 36                 // 36 % 32 = 4 -> conflict-free fragment loads

// -------------------- scratch (device globals; no allocs) --------------------
__device__ __align__(16) float    g_h  [NN*HH];
__device__ __align__(16) float    g_hg [NN*HH];
__device__ __align__(16) float    g_qk [NN*HH];
__device__ __align__(16) float    g_att[NN*HH];
__device__ __align__(16) float    g_out[NN*HH];
__device__ __align__(16) float    g_hn [NN*HH];
__device__ __align__(16) float    g_up [NN*HFF];
__device__ __align__(16) float    g_dn [NN*HH];
__device__ float    g_deg[NN];
__device__ int      g_starts[BB+1];
__device__ int      g_pos[NN];
__device__ unsigned g_adj[ADJTOT];

__device__ __forceinline__ float sigf(float x){ return 1.f/(1.f+__expf(-x)); }

__device__ __forceinline__ void cpa16(float* s, const float* g){
    unsigned a = (unsigned)__cvta_generic_to_shared(s);
    asm volatile("cp.async.cg.shared.global [%0], [%1], 16;" :: "r"(a), "l"(g));
}
__device__ __forceinline__ void cpa_commit(){ asm volatile("cp.async.commit_group;"); }
template<int N> __device__ __forceinline__ void cpa_wait(){
    asm volatile("cp.async.wait_group %0;" :: "n"(N));
}

// -------------------- graph structure --------------------
__global__ void clear_adj_k(unsigned* __restrict__ adj){
    size_t i = (size_t)blockIdx.x*blockDim.x + threadIdx.x;
    if (i < ADJTOT) adj[i] = 0u;
}

__global__ void starts_k(const int* __restrict__ batch, int* __restrict__ starts){
    int n = blockIdx.x*blockDim.x + threadIdx.x;
    if (n >= NN) return;
    if (n == 0){ starts[batch[0]] = 0; starts[BB] = NN; }
    else if (batch[n] != batch[n-1]) starts[batch[n]] = n;
}

__global__ void pos_self_k(const int* __restrict__ batch, const int* __restrict__ starts,
                           int* __restrict__ pos, unsigned* __restrict__ adj){
    int n = blockIdx.x*blockDim.x + threadIdx.x;
    if (n >= NN) return;
    int b = batch[n];
    int p = n - starts[b];
    pos[n] = p;
    atomicOr(&adj[((size_t)b*NMAX + p)*ADJW + (p>>5)], 1u << (p&31));
}

__global__ void edge_k(const int* __restrict__ ei, const int* __restrict__ batch,
                       const int* __restrict__ pos, unsigned* __restrict__ adj){
    int e = blockIdx.x*blockDim.x + threadIdx.x;
    if (e >= EE) return;
    int s = ei[e];
    int d = ei[EE + e];
    int b = batch[s];
    int ps = pos[s], pd = pos[d];
    atomicOr(&adj[((size_t)b*NMAX + ps)*ADJW + (pd>>5)], 1u << (pd&31));
}

__global__ void deg_k(const int* __restrict__ batch, const int* __restrict__ pos,
                      const unsigned* __restrict__ adj, float* __restrict__ deg){
    int n = blockIdx.x*blockDim.x + threadIdx.x;
    if (n >= NN) return;
    int b = batch[n];
    const unsigned* row = adj + ((size_t)b*NMAX + pos[n])*ADJW;
    int c = 0;
    #pragma unroll
    for (int w = 0; w < ADJW; w++) c += __popc(row[w]);
    deg[n] = (float)c;
}

// -------------------- TF32 tensor-core GEMM, cp.async double-buffered --------
// C = A@W (+ A2@W2 if DUAL) (+bias) (sigmoid?).  Row-major everywhere.
// Block tile 128xBN_, BK=32, 2-stage cp.async pipeline.
// 8 warps as 4(row)x2(col): warp tile 32 x (BN_/2) -> 2 x NF wmma frags.
template<int BN_, bool DUAL>
__global__ void __launch_bounds__(256, 2)
gemm_tc(const float* __restrict__ A, int lda, long long sAz,
        const float* __restrict__ W, int ldw, long long sWz,
        const float* __restrict__ A2, const float* __restrict__ W2,
        float*       __restrict__ C, int ldc, long long sCz,
        const float* __restrict__ bias, long long sBz,
        int K, int flags)
{
    constexpr int LDB  = BN_ + 4;          // 132 or 68 (≡4 mod 32 banks)
    constexpr int LDC_ = BN_ + 4;
    constexpr int ASZ  = BM * LDA_S;       // 4608 floats
    constexpr int BSZ  = BK * LDB;
    constexpr int STG  = ASZ + BSZ;
    constexpr int NF   = BN_ / 32;         // frags per warp in N (4 or 2)
    constexpr int BF4  = (BK * BN_) / 4 / 256;   // float4 per thread for B tile
    constexpr int BROW4= BN_ / 4;          // float4 per B row

    A += (size_t)blockIdx.z * sAz;
    W += (size_t)blockIdx.z * sWz;
    C += (size_t)blockIdx.z * sCz;
    if (bias) bias += (size_t)blockIdx.z * sBz;

    extern __shared__ __align__(16) float sm[];

    int tid  = threadIdx.x;
    int warp = tid >> 5;
    int wm   = warp >> 1;   // 0..3 -> 32-row group
    int wn   = warp & 1;    // 0..1 -> (BN_/2)-col group
    int row0 = blockIdx.y * BM;
    int col0 = blockIdx.x * BN_;

    // loaders: A 2 thr/row x 16 floats; B flat float4 indexing
    int ar  = tid >> 1,  ac0 = (tid & 1) * 16;

    wmma::fragment<wmma::accumulator, 16, 16, 8, float> acc[2][NF];
    #pragma unroll
    for (int i = 0; i < 2; i++)
        #pragma unroll
        for (int j = 0; j < NF; j++)
            wmma::fill_fragment(acc[i][j], 0.0f);

    const int T = K / BK;

    #pragma unroll
    for (int phase = 0; phase < (DUAL ? 2 : 1); phase++){
        const float* Ap = (DUAL && phase) ? A2 : A;
        const float* Wp = (DUAL && phase) ? W2 : W;

        // prefetch tile 0 into stage 0
        {
            float* As = sm;
            float* Bs = sm + ASZ;
            const float* ag = Ap + (size_t)(row0 + ar)*lda + ac0;
            #pragma unroll
            for (int i = 0; i < 4; i++) cpa16(&As[ar*LDA_S + ac0 + i*4], ag + i*4);
            #pragma unroll
            for (int i = 0; i < BF4; i++){
                int f = tid + i*256;
                int brow = f / BROW4, bcol = (f % BROW4) * 4;
                cpa16(&Bs[brow*LDB + bcol], Wp + (size_t)brow*ldw + col0 + bcol);
            }
            cpa_commit();
        }

        for (int it = 0; it < T; it++){
            int cur = it & 1;
            if (it + 1 < T){
                int nxt = cur ^ 1;
                float* As = sm + nxt*STG;
                float* Bs = As + ASZ;
                int k0 = (it + 1) * BK;
                const float* ag = Ap + (size_t)(row0 + ar)*lda + k0 + ac0;
                #pragma unroll
                for (int i = 0; i < 4; i++) cpa16(&As[ar*LDA_S + ac0 + i*4], ag + i*4);
                #pragma unroll
                for (int i = 0; i < BF4; i++){
                    int f = tid + i*256;
                    int brow = f / BROW4, bcol = (f % BROW4) * 4;
                    cpa16(&Bs[brow*LDB + bcol], Wp + (size_t)(k0 + brow)*ldw + col0 + bcol);
                }
                cpa_commit();
                cpa_wait<1>();
            } else {
                cpa_wait<0>();
            }
            __syncthreads();

            float* As = sm + cur*STG;
            float* Bs = As + ASZ;
            #pragma unroll
            for (int kk = 0; kk < BK; kk += 8){
                wmma::fragment<wmma::matrix_a, 16, 16, 8, wmma::precision::tf32, wmma::row_major> fa[2];
                wmma::fragment<wmma::matrix_b, 16, 16, 8, wmma::precision::tf32, wmma::row_major> fb[NF];
                #pragma unroll
                for (int i = 0; i < 2; i++){
                    wmma::load_matrix_sync(fa[i], &As[(wm*32 + i*16)*LDA_S + kk], LDA_S);
                    #pragma unroll
                    for (int t = 0; t < fa[i].num_elements; t++)
                        fa[i].x[t] = wmma::__float_to_tf32(fa[i].x[t]);
                }
                #pragma unroll
                for (int j = 0; j < NF; j++){
                    wmma::load_matrix_sync(fb[j], &Bs[kk*LDB + wn*(16*NF) + j*16], LDB);
                    #pragma unroll
                    for (int t = 0; t < fb[j].num_elements; t++)
                        fb[j].x[t] = wmma::__float_to_tf32(fb[j].x[t]);
                }
                #pragma unroll
                for (int i = 0; i < 2; i++)
                    #pragma unroll
                    for (int j = 0; j < NF; j++)
                        wmma::mma_sync(acc[i][j], fa[i], fb[j], acc[i][j]);
            }
            __syncthreads();
        }
    }

    // epilogue via smem (reuses pipeline staging)
    #pragma unroll
    for (int i = 0; i < 2; i++)
        #pragma unroll
        for (int j = 0; j < NF; j++)
            wmma::store_matrix_sync(&sm[(wm*32 + i*16)*LDC_ + wn*(16*NF) + j*16],
                                    acc[i][j], LDC_, wmma::mem_row_major);
    __syncthreads();

    int er   = tid >> 1;                 // 0..127
    int ecol = (tid & 1) * (BN_/2);
    #pragma unroll
    for (int i = 0; i < BN_/8; i++){
        int cc = ecol + i*4;
        float4 v = *(const float4*)&sm[er*LDC_ + cc];
        size_t gr = (size_t)(row0 + er)*ldc + col0 + cc;
        if (bias){
            v.x += bias[col0+cc+0]; v.y += bias[col0+cc+1];
            v.z += bias[col0+cc+2]; v.w += bias[col0+cc+3];
        }
        if (flags & FLAG_ACC){
            float4 c0 = *(const float4*)(C + gr);
            v.x += c0.x; v.y += c0.y; v.z += c0.z; v.w += c0.w;
        }
        if (flags & FLAG_SIG){
            v.x = sigf(v.x); v.y = sigf(v.y); v.z = sigf(v.z); v.w = sigf(v.w);
        }
        *(float4*)(C + gr) = v;
    }
}

#define SMEM_128 (2*(BM*LDA_S + BK*(128+4))*(int)sizeof(float))   // 70656
#define SMEM_64  (2*(BM*LDA_S + BK*(64+4))*(int)sizeof(float))    // 54272

// -------------------- elementwise / reductions --------------------
__global__ void gate_k(const float* __restrict__ h, const float* __restrict__ deg,
                       const float* __restrict__ Wd, const float* __restrict__ bd,
                       float* __restrict__ hg){
    int n = blockIdx.x, t = threadIdx.x;  // 128 threads, float4 each
    float d = deg[n];
    float4 hv = ((const float4*)(h + (size_t)n*HH))[t];
    float4 wv = ((const float4*)Wd)[t];
    float4 bv = ((const float4*)bd)[t];
    float4 o;
    o.x = hv.x * sigf(d*wv.x + bv.x);
    o.y = hv.y * sigf(d*wv.y + bv.y);
    o.z = hv.z * sigf(d*wv.z + bv.z);
    o.w = hv.w * sigf(d*wv.w + bv.w);
    ((float4*)(hg + (size_t)n*HH))[t] = o;
}

// sparse masked attention: warp per node
__global__ void attn_k(const float* __restrict__ qk, const float* __restrict__ hg,
                       const unsigned* __restrict__ adj, const int* __restrict__ starts,
                       const int* __restrict__ batch, float* __restrict__ out){
    int warp = (blockIdx.x*blockDim.x + threadIdx.x) >> 5;
    int lane = threadIdx.x & 31;
    if (warp >= NN) return;
    int n = warp;
    int b = batch[n];
    int start = starts[b];
    int p = n - start;
    const unsigned* row = adj + ((size_t)b*NMAX + p)*ADJW;
    const float4* qn4 = (const float4*)(qk + (size_t)n*HH);
    float4 qn[4];
    #pragma unroll
    for (int c = 0; c < 4; c++) qn[c] = qn4[lane + c*32];
    float4 acc[4] = {{0,0,0,0},{0,0,0,0},{0,0,0,0},{0,0,0,0}};
    float rowsum = 0.f;
    const float inv_sqrt_h = 0.044194173824159216f; // 1/sqrt(512)

    for (int w = 0; w < ADJW; w++){
        unsigned bits = row[w];
        while (bits){
            int t = __ffs((int)bits) - 1; bits &= bits - 1;
            int m = start + w*32 + t;
            const float4* qm4 = (const float4*)(qk + (size_t)m*HH);
            float s = 0.f;
            #pragma unroll
            for (int c = 0; c < 4; c++){
                float4 v = qm4[lane + c*32];
                s += qn[c].x*v.x + qn[c].y*v.y + qn[c].z*v.z + qn[c].w*v.w;
            }
            #pragma unroll
            for (int o = 16; o; o >>= 1) s += __shfl_xor_sync(0xffffffffu, s, o);
            s *= inv_sqrt_h;
            rowsum += s;
            const float4* hm4 = (const float4*)(hg + (size_t)m*HH);
            #pragma unroll
            for (int c = 0; c < 4; c++){
                float4 hv = hm4[lane + c*32];
                acc[c].x += s*hv.x; acc[c].y += s*hv.y;
                acc[c].z += s*hv.z; acc[c].w += s*hv.w;
            }
        }
    }
    float inv = 1.f/(rowsum + 1e-6f);
    float4* o4 = (float4*)(out + (size_t)n*HH);
    #pragma unroll
    for (int c = 0; c < 4; c++){
        acc[c].x *= inv; acc[c].y *= inv; acc[c].z *= inv; acc[c].w *= inv;
        o4[lane + c*32] = acc[c];
    }
}

// l2-normalize rows then relu
__global__ void l2relu_k(const float* __restrict__ x, float* __restrict__ y){
    int n = blockIdx.x, t = threadIdx.x; // 128 threads, float4 each
    float4 v = ((const float4*)(x + (size_t)n*HH))[t];
    float ss = v.x*v.x + v.y*v.y + v.z*v.z + v.w*v.w;
    #pragma unroll
    for (int o = 16; o; o >>= 1) ss += __shfl_xor_sync(0xffffffffu, ss, o);
    __shared__ float sh[4];
    __shared__ float sinv;
    int w = t >> 5, l = t & 31;
    if (l == 0) sh[w] = ss;
    __syncthreads();
    if (t == 0){
        float tot = sh[0] + sh[1] + sh[2] + sh[3];
        sinv = 1.f / fmaxf(sqrtf(tot), 1e-12f);
    }
    __syncthreads();
    float iv = sinv;
    float4 o;
    o.x = fmaxf(v.x*iv, 0.f); o.y = fmaxf(v.y*iv, 0.f);
    o.z = fmaxf(v.z*iv, 0.f); o.w = fmaxf(v.w*iv, 0.f);
    ((float4*)(y + (size_t)n*HH))[t] = o;
}

// layernorm over width W, NT threads/row; optional fused relu; in-place safe
template<int W, int NT, bool RELU>
__global__ void ln_k(const float* __restrict__ x, float* __restrict__ y,
                     const float* __restrict__ g, const float* __restrict__ b){
    constexpr int PT = W / NT;
    int row = blockIdx.x, t = threadIdx.x;
    const float* xr = x + (size_t)row*W;
    float*       yr = y + (size_t)row*W;
    float v[PT]; float s = 0.f, s2 = 0.f;
    #pragma unroll
    for (int i = 0; i < PT; i++){ float u = xr[t + i*NT]; v[i] = u; s += u; s2 += u*u; }
    #pragma unroll
    for (int o = 16; o; o >>= 1){
        s  += __shfl_xor_sync(0xffffffffu, s,  o);
        s2 += __shfl_xor_sync(0xffffffffu, s2, o);
    }
    __shared__ float sh[2][NT/32];
    __shared__ float mb[2];
    int w = t >> 5, l = t & 31;
    if (l == 0){ sh[0][w] = s; sh[1][w] = s2; }
    __syncthreads();
    if (t == 0){
        float ts = 0.f, ts2 = 0.f;
        #pragma unroll
        for (int i = 0; i < NT/32; i++){ ts += sh[0][i]; ts2 += sh[1][i]; }
        float mean = ts / W;
        float var  = ts2 / W - mean*mean;
        mb[0] = mean; mb[1] = rsqrtf(var + 1e-5f);
    }
    __syncthreads();
    float mean = mb[0], rstd = mb[1];
    #pragma unroll
    for (int i = 0; i < PT; i++){
        int c = t + i*NT;
        float o = (v[i] - mean) * rstd * g[c] + b[c];
        if (RELU) o = fmaxf(o, 0.f);
        yr[c] = o;
    }
}

__global__ void res_k(float* __restrict__ h, const float* __restrict__ dn,
                      const float* __restrict__ gamma){
    int n = blockIdx.x, t = threadIdx.x;
    float4 hv = ((const float4*)(h + (size_t)n*HH))[t];
    float4 dv = ((const float4*)(dn + (size_t)n*HH))[t];
    float4 gm = ((const float4*)gamma)[t];
    hv.x += gm.x*dv.x; hv.y += gm.y*dv.y; hv.z += gm.z*dv.z; hv.w += gm.w*dv.w;
    ((float4*)(h + (size_t)n*HH))[t] = hv;
}

__global__ void pool_k(const float* __restrict__ h, const int* __restrict__ starts,
                       float* __restrict__ out){
    int b = blockIdx.x;
    int f = blockIdx.y*128 + threadIdx.x;
    int s = starts[b], e = starts[b+1];
    float acc = 0.f;
    for (int n = s; n < e; n++) acc += h[(size_t)n*HH + f];
    out[(size_t)b*HH + f] = acc;
}

// -------------------- launcher --------------------
extern "C" void kernel_launch(void* const* d_in, const int* in_sizes, int n_in,
                              void* d_out, int out_size){
    const float* x     = (const float*)d_in[0];
    const int*   ei    = (const int*)d_in[1];     // int32 per harness dtype contract
    const int*   batch = (const int*)d_in[2];     // int32 per harness dtype contract
    const float* W_in = (const float*)d_in[3];
    const float* b_in = (const float*)d_in[4];
    const float* Wqk  = (const float*)d_in[5];
    const float* bqk  = (const float*)d_in[6];
    const float* Wd   = (const float*)d_in[7];
    const float* bd   = (const float*)d_in[8];
    const float* Wl   = (const float*)d_in[9];
    const float* bl   = (const float*)d_in[10];
    const float* Wr   = (const float*)d_in[11];
    const float* gamma= (const float*)d_in[12];
    const float* ln_g = (const float*)d_in[13];
    const float* ln_b = (const float*)d_in[14];
    const float* up_w = (const float*)d_in[15];
    const float* up_b = (const float*)d_in[16];
    const float* up_lg= (const float*)d_in[17];
    const float* up_lb= (const float*)d_in[18];
    const float* dn_w = (const float*)d_in[19];
    const float* dn_b = (const float*)d_in[20];
    const float* dn_lg= (const float*)d_in[21];
    const float* dn_lb= (const float*)d_in[22];
    float* out = (float*)d_out;

    float *h, *hg, *qk, *att, *ob, *hn, *up, *dn, *deg;
    int *starts, *pos; unsigned* adj;
    cudaGetSymbolAddress((void**)&h,   g_h);
    cudaGetSymbolAddress((void**)&hg,  g_hg);
    cudaGetSymbolAddress((void**)&qk,  g_qk);
    cudaGetSymbolAddress((void**)&att, g_att);
    cudaGetSymbolAddress((void**)&ob,  g_out);
    cudaGetSymbolAddress((void**)&hn,  g_hn);
    cudaGetSymbolAddress((void**)&up,  g_up);
    cudaGetSymbolAddress((void**)&dn,  g_dn);
    cudaGetSymbolAddress((void**)&deg, g_deg);
    cudaGetSymbolAddress((void**)&starts, g_starts);
    cudaGetSymbolAddress((void**)&pos,    g_pos);
    cudaGetSymbolAddress((void**)&adj,    g_adj);

    // opt-in to >48KB dynamic smem (idempotent; capture-safe)
    cudaFuncSetAttribute((const void*)gemm_tc<128,false>,
                         cudaFuncAttributeMaxDynamicSharedMemorySize, SMEM_128);
    cudaFuncSetAttribute((const void*)gemm_tc<128,true>,
                         cudaFuncAttributeMaxDynamicSharedMemorySize, SMEM_128);
    cudaFuncSetAttribute((const void*)gemm_tc<64,false>,
                         cudaFuncAttributeMaxDynamicSharedMemorySize, SMEM_64);

    // graph structure (ordered so the first GEMM is launch #5 incl. harness -> ncu -s 5 hits it)
    clear_adj_k<<<(int)((ADJTOT + 255)/256), 256>>>(adj);
    starts_k  <<<NN/256, 256>>>(batch, starts);
    pos_self_k<<<NN/256, 256>>>(batch, starts, pos, adj);

    // h = x @ W_in + b_in   (no graph-structure dependency)
    gemm_tc<128,false><<<dim3(HH/128, NN/BM, 1), 256, SMEM_128>>>(
        x, FF, 0, W_in, HH, 0, nullptr, nullptr, h, HH, 0, b_in, 0, FF, 0);

    edge_k    <<<EE/256, 256>>>(ei, batch, pos, adj);
    deg_k     <<<NN/256, 256>>>(batch, pos, adj, deg);

    for (int l = 0; l < LL; l++){
        gate_k<<<NN, 128>>>(h, deg, Wd + l*HH, bd + l*HH, hg);
        gemm_tc<128,false><<<dim3(HH/128, NN/BM, 1), 256, SMEM_128>>>(
            hg, HH, 0, Wqk + (size_t)l*HH*HH, HH, 0, nullptr, nullptr,
            qk, HH, 0, bqk + l*HH, 0, HH, FLAG_SIG);
        attn_k<<<NN/8, 256>>>(qk, hg, adj, starts, batch, att);
        // ob = att@Wl + hg@Wr + bl  (fused dual GEMM)
        gemm_tc<128,true><<<dim3(HH/128, NN/BM, 1), 256, SMEM_128>>>(
            att, HH, 0, Wl + (size_t)l*HH*HH, HH, 0,
            hg, Wr + (size_t)l*HH*HH,
            ob, HH, 0, bl + l*HH, 0, HH, 0);
        l2relu_k<<<NN, 128>>>(ob, h);
        ln_k<HH, 128, false><<<NN, 128>>>(h, hn, ln_g + l*HH, ln_b + l*HH);
        // grouped up: per group g: [N,64]@[64,256] + b, then LN(256)+relu
        gemm_tc<128,false><<<dim3(HFG/128, NN/BM, GG), 256, SMEM_128>>>(
            hn, HH, HG,
            up_w + (size_t)l*GG*HG*HFG, HFG, (long long)HG*HFG, nullptr, nullptr,
            up, HFF, HFG,
            up_b + (size_t)l*GG*HFG, HFG, HG, 0);
        ln_k<HFG, 128, true><<<NN*GG, 128>>>(up, up, up_lg + l*HFG, up_lb + l*HFG);
        // grouped down: per group g: [N,256]@[256,64] + b, then LN(64)
        gemm_tc<64,false><<<dim3(1, NN/BM, GG), 256, SMEM_64>>>(
            up, HFF, HFG,
            dn_w + (size_t)l*GG*HFG*HG, HG, (long long)HFG*HG, nullptr, nullptr,
            dn, HH, HG,
            dn_b + (size_t)l*GG*HG, HG, HFG, 0);
        ln_k<HG, 64, false><<<NN*GG, 64>>>(dn, dn, dn_lg + l*HG, dn_lb + l*HG);
        res_k<<<NN, 128>>>(h, dn, gamma + l*HH);
    }

    pool_k<<<dim3(BB, HH/128), 128>>>(h, starts, out);
}

// round 7
// speedup vs baseline: 1.4563x; 1.0426x over previous
#include <cuda_runtime.h>
#include <cuda_bf16.h>
#include <mma.h>
#include <math.h>

using namespace nvcuda;

// Problem constants (fixed instance)
#define NN    8192
#define BB    32
#define NMAX  512
#define FF    128
#define HH    512
#define LL    3
#define GG    8
#define HFF   2048
#define EE    131072
#define HG    (HH/GG)    // 64
#define HFG   (HFF/GG)   // 256
#define ADJW  16         // 512 bits / 32
#define ADJTOT ((size_t)BB*NMAX*ADJW)

#define FLAG_ACC 1
#define FLAG_SIG 2

// GEMM tiling: BM=128, BK=32, BN templated (128 main / 64 small)
#define BM 128
#define BK 32
#define LDA_S 36                 // ≡4 mod 32 -> conflict-free fragment loads

// -------------------- scratch (device globals; no allocs) --------------------
__device__ __align__(16) float    g_h  [NN*HH];
__device__ __align__(16) float    g_hg [NN*HH];
__device__ __align__(16) float    g_qk [NN*HH];
__device__ __align__(16) float    g_att[NN*HH];
__device__ __align__(16) float    g_out[NN*HH];
__device__ __align__(16) float    g_hn [NN*HH];
__device__ __align__(16) float    g_up [NN*HFF];
__device__ __align__(16) float    g_dn [NN*HH];
__device__ float    g_deg[NN];
__device__ int      g_starts[BB+1];
__device__ int      g_pos[NN];
__device__ unsigned g_adj[ADJTOT];

__device__ __forceinline__ float sigf(float x){ return 1.f/(1.f+__expf(-x)); }

__device__ __forceinline__ void cpa16(float* s, const float* g){
    unsigned a = (unsigned)__cvta_generic_to_shared(s);
    asm volatile("cp.async.cg.shared.global [%0], [%1], 16;" :: "r"(a), "l"(g));
}
__device__ __forceinline__ void cpa_commit(){ asm volatile("cp.async.commit_group;"); }
template<int N> __device__ __forceinline__ void cpa_wait(){
    asm volatile("cp.async.wait_group %0;" :: "n"(N));
}

// -------------------- graph structure --------------------
__global__ void clear_adj_k(unsigned* __restrict__ adj){
    size_t i = (size_t)blockIdx.x*blockDim.x + threadIdx.x;
    if (i < ADJTOT) adj[i] = 0u;
}

__global__ void starts_k(const int* __restrict__ batch, int* __restrict__ starts){
    int n = blockIdx.x*blockDim.x + threadIdx.x;
    if (n >= NN) return;
    if (n == 0){ starts[batch[0]] = 0; starts[BB] = NN; }
    else if (batch[n] != batch[n-1]) starts[batch[n]] = n;
}

__global__ void pos_self_k(const int* __restrict__ batch, const int* __restrict__ starts,
                           int* __restrict__ pos, unsigned* __restrict__ adj){
    int n = blockIdx.x*blockDim.x + threadIdx.x;
    if (n >= NN) return;
    int b = batch[n];
    int p = n - starts[b];
    pos[n] = p;
    atomicOr(&adj[((size_t)b*NMAX + p)*ADJW + (p>>5)], 1u << (p&31));
}

__global__ void edge_k(const int* __restrict__ ei, const int* __restrict__ batch,
                       const int* __restrict__ pos, unsigned* __restrict__ adj){
    int e = blockIdx.x*blockDim.x + threadIdx.x;
    if (e >= EE) return;
    int s = ei[e];
    int d = ei[EE + e];
    int b = batch[s];
    int ps = pos[s], pd = pos[d];
    atomicOr(&adj[((size_t)b*NMAX + ps)*ADJW + (pd>>5)], 1u << (pd&31));
}

__global__ void deg_k(const int* __restrict__ batch, const int* __restrict__ pos,
                      const unsigned* __restrict__ adj, float* __restrict__ deg){
    int n = blockIdx.x*blockDim.x + threadIdx.x;
    if (n >= NN) return;
    int b = batch[n];
    const unsigned* row = adj + ((size_t)b*NMAX + pos[n])*ADJW;
    int c = 0;
    #pragma unroll
    for (int w = 0; w < ADJW; w++) c += __popc(row[w]);
    deg[n] = (float)c;
}

// -------------------- TF32 tensor-core GEMM, 3-stage cp.async pipeline -------
// C = A@W (+ A2@W2 if DUAL) (+bias) (sigmoid?).  Row-major everywhere.
// Block tile 128xBN_, BK=32.  8 warps as 4(row)x2(col): warp tile 32x(BN_/2).
// Raw fp32 in tf32 fragments: HMMA.TF32 truncates mantissa in HW (no cvt ops).
// One __syncthreads per tile: wait -> sync -> prefetch(it+2) -> mma.
template<int BN_, bool DUAL>
__global__ void __launch_bounds__(256, 2)
gemm_tc(const float* __restrict__ A, int lda, long long sAz,
        const float* __restrict__ W, int ldw, long long sWz,
        const float* __restrict__ A2, const float* __restrict__ W2,
        float*       __restrict__ C, int ldc, long long sCz,
        const float* __restrict__ bias, long long sBz,
        int K, int flags)
{
    constexpr int LDB  = BN_ + 4;
    constexpr int LDC_ = BN_ + 4;
    constexpr int ASZ  = BM * LDA_S;
    constexpr int BSZ  = BK * LDB;
    constexpr int STG  = ASZ + BSZ;
    constexpr int NF   = BN_ / 32;
    constexpr int BF4  = (BK * BN_) / 4 / 256;
    constexpr int BROW4= BN_ / 4;

    A += (size_t)blockIdx.z * sAz;
    W += (size_t)blockIdx.z * sWz;
    C += (size_t)blockIdx.z * sCz;
    if (bias) bias += (size_t)blockIdx.z * sBz;

    extern __shared__ __align__(16) float sm[];

    int tid  = threadIdx.x;
    int warp = tid >> 5;
    int wm   = warp >> 1;
    int wn   = warp & 1;
    int row0 = blockIdx.y * BM;
    int col0 = blockIdx.x * BN_;

    int ar  = tid >> 1,  ac0 = (tid & 1) * 16;

    wmma::fragment<wmma::accumulator, 16, 16, 8, float> acc[2][NF];
    #pragma unroll
    for (int i = 0; i < 2; i++)
        #pragma unroll
        for (int j = 0; j < NF; j++)
            wmma::fill_fragment(acc[i][j], 0.0f);

    const int T  = K / BK;
    const int TT = DUAL ? 2*T : T;

    // prefetch j-th logical tile into stage j%3
    auto prefetch = [&](int j){
        const float* Ap = (DUAL && j >= T) ? A2 : A;
        const float* Wp = (DUAL && j >= T) ? W2 : W;
        int k0 = (DUAL ? (j % T) : j) * BK;
        float* As = sm + (j % 3)*STG;
        float* Bs = As + ASZ;
        const float* ag = Ap + (size_t)(row0 + ar)*lda + k0 + ac0;
        #pragma unroll
        for (int i = 0; i < 4; i++) cpa16(&As[ar*LDA_S + ac0 + i*4], ag + i*4);
        #pragma unroll
        for (int i = 0; i < BF4; i++){
            int f = tid + i*256;
            int brow = f / BROW4, bcol = (f % BROW4) * 4;
            cpa16(&Bs[brow*LDB + bcol], Wp + (size_t)(k0 + brow)*ldw + col0 + bcol);
        }
        cpa_commit();
    };

    prefetch(0);
    if (TT > 1) prefetch(1);

    for (int it = 0; it < TT; it++){
        if (it + 1 < TT) cpa_wait<1>(); else cpa_wait<0>();
        __syncthreads();
        if (it + 2 < TT) prefetch(it + 2);

        float* As = sm + (it % 3)*STG;
        float* Bs = As + ASZ;
        #pragma unroll
        for (int kk = 0; kk < BK; kk += 8){
            wmma::fragment<wmma::matrix_a, 16, 16, 8, wmma::precision::tf32, wmma::row_major> fa[2];
            wmma::fragment<wmma::matrix_b, 16, 16, 8, wmma::precision::tf32, wmma::row_major> fb[NF];
            #pragma unroll
            for (int i = 0; i < 2; i++)
                wmma::load_matrix_sync(fa[i], &As[(wm*32 + i*16)*LDA_S + kk], LDA_S);
            #pragma unroll
            for (int j = 0; j < NF; j++)
                wmma::load_matrix_sync(fb[j], &Bs[kk*LDB + wn*(16*NF) + j*16], LDB);
            #pragma unroll
            for (int i = 0; i < 2; i++)
                #pragma unroll
                for (int j = 0; j < NF; j++)
                    wmma::mma_sync(acc[i][j], fa[i], fb[j], acc[i][j]);
        }
    }
    __syncthreads();   // before reusing sm for C staging

    #pragma unroll
    for (int i = 0; i < 2; i++)
        #pragma unroll
        for (int j = 0; j < NF; j++)
            wmma::store_matrix_sync(&sm[(wm*32 + i*16)*LDC_ + wn*(16*NF) + j*16],
                                    acc[i][j], LDC_, wmma::mem_row_major);
    __syncthreads();

    int er   = tid >> 1;
    int ecol = (tid & 1) * (BN_/2);
    #pragma unroll
    for (int i = 0; i < BN_/8; i++){
        int cc = ecol + i*4;
        float4 v = *(const float4*)&sm[er*LDC_ + cc];
        size_t gr = (size_t)(row0 + er)*ldc + col0 + cc;
        if (bias){
            v.x += bias[col0+cc+0]; v.y += bias[col0+cc+1];
            v.z += bias[col0+cc+2]; v.w += bias[col0+cc+3];
        }
        if (flags & FLAG_ACC){
            float4 c0 = *(const float4*)(C + gr);
            v.x += c0.x; v.y += c0.y; v.z += c0.z; v.w += c0.w;
        }
        if (flags & FLAG_SIG){
            v.x = sigf(v.x); v.y = sigf(v.y); v.z = sigf(v.z); v.w = sigf(v.w);
        }
        *(float4*)(C + gr) = v;
    }
}

#define SMEM_128 (3*(BM*LDA_S + BK*(128+4))*(int)sizeof(float))   // 105984
#define SMEM_64  (3*(BM*LDA_S + BK*(64+4))*(int)sizeof(float))    // 81408

// -------------------- elementwise / reductions --------------------
__global__ void gate_k(const float* __restrict__ h, const float* __restrict__ deg,
                       const float* __restrict__ Wd, const float* __restrict__ bd,
                       float* __restrict__ hg){
    int n = blockIdx.x, t = threadIdx.x;  // 128 threads, float4 each
    float d = deg[n];
    float4 hv = ((const float4*)(h + (size_t)n*HH))[t];
    float4 wv = ((const float4*)Wd)[t];
    float4 bv = ((const float4*)bd)[t];
    float4 o;
    o.x = hv.x * sigf(d*wv.x + bv.x);
    o.y = hv.y * sigf(d*wv.y + bv.y);
    o.z = hv.z * sigf(d*wv.z + bv.z);
    o.w = hv.w * sigf(d*wv.w + bv.w);
    ((float4*)(hg + (size_t)n*HH))[t] = o;
}

// sparse masked attention: warp per node
__global__ void attn_k(const float* __restrict__ qk, const float* __restrict__ hg,
                       const unsigned* __restrict__ adj, const int* __restrict__ starts,
                       const int* __restrict__ batch, float* __restrict__ out){
    int warp = (blockIdx.x*blockDim.x + threadIdx.x) >> 5;
    int lane = threadIdx.x & 31;
    if (warp >= NN) return;
    int n = warp;
    int b = batch[n];
    int start = starts[b];
    int p = n - start;
    const unsigned* row = adj + ((size_t)b*NMAX + p)*ADJW;
    const float4* qn4 = (const float4*)(qk + (size_t)n*HH);
    float4 qn[4];
    #pragma unroll
    for (int c = 0; c < 4; c++) qn[c] = qn4[lane + c*32];
    float4 acc[4] = {{0,0,0,0},{0,0,0,0},{0,0,0,0},{0,0,0,0}};
    float rowsum = 0.f;
    const float inv_sqrt_h = 0.044194173824159216f; // 1/sqrt(512)

    for (int w = 0; w < ADJW; w++){
        unsigned bits = row[w];
        while (bits){
            int t = __ffs((int)bits) - 1; bits &= bits - 1;
            int m = start + w*32 + t;
            const float4* qm4 = (const float4*)(qk + (size_t)m*HH);
            float s = 0.f;
            #pragma unroll
            for (int c = 0; c < 4; c++){
                float4 v = qm4[lane + c*32];
                s += qn[c].x*v.x + qn[c].y*v.y + qn[c].z*v.z + qn[c].w*v.w;
            }
            #pragma unroll
            for (int o = 16; o; o >>= 1) s += __shfl_xor_sync(0xffffffffu, s, o);
            s *= inv_sqrt_h;
            rowsum += s;
            const float4* hm4 = (const float4*)(hg + (size_t)m*HH);
            #pragma unroll
            for (int c = 0; c < 4; c++){
                float4 hv = hm4[lane + c*32];
                acc[c].x += s*hv.x; acc[c].y += s*hv.y;
                acc[c].z += s*hv.z; acc[c].w += s*hv.w;
            }
        }
    }
    float inv = 1.f/(rowsum + 1e-6f);
    float4* o4 = (float4*)(out + (size_t)n*HH);
    #pragma unroll
    for (int c = 0; c < 4; c++){
        acc[c].x *= inv; acc[c].y *= inv; acc[c].z *= inv; acc[c].w *= inv;
        o4[lane + c*32] = acc[c];
    }
}

// fused: h = relu(l2norm(ob)); hn = LN(h)*g+b     (width 512, 128 thr x float4)
__global__ void l2ln_k(const float* __restrict__ x, float* __restrict__ h,
                       float* __restrict__ hn, const float* __restrict__ g,
                       const float* __restrict__ b){
    int n = blockIdx.x, t = threadIdx.x;
    float4 v = ((const float4*)(x + (size_t)n*HH))[t];
    float ss = v.x*v.x + v.y*v.y + v.z*v.z + v.w*v.w;
    #pragma unroll
    for (int o = 16; o; o >>= 1) ss += __shfl_xor_sync(0xffffffffu, ss, o);
    __shared__ float sh[4], sh2[4], red[3];
    int w = t >> 5, l = t & 31;
    if (l == 0) sh[w] = ss;
    __syncthreads();
    if (t == 0) red[0] = 1.f / fmaxf(sqrtf(sh[0]+sh[1]+sh[2]+sh[3]), 1e-12f);
    __syncthreads();
    float iv = red[0];
    float4 hv;
    hv.x = fmaxf(v.x*iv, 0.f); hv.y = fmaxf(v.y*iv, 0.f);
    hv.z = fmaxf(v.z*iv, 0.f); hv.w = fmaxf(v.w*iv, 0.f);
    ((float4*)(h + (size_t)n*HH))[t] = hv;
    float s  = hv.x + hv.y + hv.z + hv.w;
    float s2 = hv.x*hv.x + hv.y*hv.y + hv.z*hv.z + hv.w*hv.w;
    #pragma unroll
    for (int o = 16; o; o >>= 1){
        s  += __shfl_xor_sync(0xffffffffu, s,  o);
        s2 += __shfl_xor_sync(0xffffffffu, s2, o);
    }
    if (l == 0){ sh[w] = s; sh2[w] = s2; }
    __syncthreads();
    if (t == 0){
        float ts = sh[0]+sh[1]+sh[2]+sh[3], ts2 = sh2[0]+sh2[1]+sh2[2]+sh2[3];
        float mean = ts / HH;
        red[1] = mean; red[2] = rsqrtf(ts2/HH - mean*mean + 1e-5f);
    }
    __syncthreads();
    float mean = red[1], rstd = red[2];
    float4 gv = ((const float4*)g)[t];
    float4 bv = ((const float4*)b)[t];
    float4 o;
    o.x = (hv.x-mean)*rstd*gv.x + bv.x;
    o.y = (hv.y-mean)*rstd*gv.y + bv.y;
    o.z = (hv.z-mean)*rstd*gv.z + bv.z;
    o.w = (hv.w-mean)*rstd*gv.w + bv.w;
    ((float4*)(hn + (size_t)n*HH))[t] = o;
}

// layernorm over width W, NT threads/row; optional fused relu; in-place safe
template<int W, int NT, bool RELU>
__global__ void ln_k(const float* __restrict__ x, float* __restrict__ y,
                     const float* __restrict__ g, const float* __restrict__ b){
    constexpr int PT = W / NT;
    int row = blockIdx.x, t = threadIdx.x;
    const float* xr = x + (size_t)row*W;
    float*       yr = y + (size_t)row*W;
    float v[PT]; float s = 0.f, s2 = 0.f;
    #pragma unroll
    for (int i = 0; i < PT; i++){ float u = xr[t + i*NT]; v[i] = u; s += u; s2 += u*u; }
    #pragma unroll
    for (int o = 16; o; o >>= 1){
        s  += __shfl_xor_sync(0xffffffffu, s,  o);
        s2 += __shfl_xor_sync(0xffffffffu, s2, o);
    }
    __shared__ float sh[2][NT/32];
    __shared__ float mb[2];
    int w = t >> 5, l = t & 31;
    if (l == 0){ sh[0][w] = s; sh[1][w] = s2; }
    __syncthreads();
    if (t == 0){
        float ts = 0.f, ts2 = 0.f;
        #pragma unroll
        for (int i = 0; i < NT/32; i++){ ts += sh[0][i]; ts2 += sh[1][i]; }
        float mean = ts / W;
        float var  = ts2 / W - mean*mean;
        mb[0] = mean; mb[1] = rsqrtf(var + 1e-5f);
    }
    __syncthreads();
    float mean = mb[0], rstd = mb[1];
    #pragma unroll
    for (int i = 0; i < PT; i++){
        int c = t + i*NT;
        float o = (v[i] - mean) * rstd * g[c] + b[c];
        if (RELU) o = fmaxf(o, 0.f);
        yr[c] = o;
    }
}

// fused: LN(64) over dn group-rows + LayerScale residual into h (same linear idx)
__global__ void ln_res_k(const float* __restrict__ dnv, float* __restrict__ h,
                         const float* __restrict__ g, const float* __restrict__ b,
                         const float* __restrict__ gamma){
    int row = blockIdx.x;            // 0..NN*GG-1
    int t   = threadIdx.x;           // 64
    float u = dnv[(size_t)row*HG + t];
    float s = u, s2 = u*u;
    #pragma unroll
    for (int o = 16; o; o >>= 1){
        s  += __shfl_xor_sync(0xffffffffu, s,  o);
        s2 += __shfl_xor_sync(0xffffffffu, s2, o);
    }
    __shared__ float sa[2], sb[2];
    int w = t >> 5, l = t & 31;
    if (l == 0){ sa[w] = s; sb[w] = s2; }
    __syncthreads();
    float ts = sa[0]+sa[1], ts2 = sb[0]+sb[1];
    float mean = ts / HG;
    float rstd = rsqrtf(ts2/HG - mean*mean + 1e-5f);
    float o = (u - mean)*rstd*g[t] + b[t];
    int gi = (row & (GG-1))*HG + t;
    h[(size_t)row*HG + t] += gamma[gi]*o;
}

__global__ void pool_k(const float* __restrict__ h, const int* __restrict__ starts,
                       float* __restrict__ out){
    int b = blockIdx.x;
    int f = blockIdx.y*128 + threadIdx.x;
    int s = starts[b], e = starts[b+1];
    float acc = 0.f;
    for (int n = s; n < e; n++) acc += h[(size_t)n*HH + f];
    out[(size_t)b*HH + f] = acc;
}

// -------------------- launcher --------------------
extern "C" void kernel_launch(void* const* d_in, const int* in_sizes, int n_in,
                              void* d_out, int out_size){
    const float* x     = (const float*)d_in[0];
    const int*   ei    = (const int*)d_in[1];
    const int*   batch = (const int*)d_in[2];
    const float* W_in = (const float*)d_in[3];
    const float* b_in = (const float*)d_in[4];
    const float* Wqk  = (const float*)d_in[5];
    const float* bqk  = (const float*)d_in[6];
    const float* Wd   = (const float*)d_in[7];
    const float* bd   = (const float*)d_in[8];
    const float* Wl   = (const float*)d_in[9];
    const float* bl   = (const float*)d_in[10];
    const float* Wr   = (const float*)d_in[11];
    const float* gamma= (const float*)d_in[12];
    const float* ln_g = (const float*)d_in[13];
    const float* ln_b = (const float*)d_in[14];
    const float* up_w = (const float*)d_in[15];
    const float* up_b = (const float*)d_in[16];
    const float* up_lg= (const float*)d_in[17];
    const float* up_lb= (const float*)d_in[18];
    const float* dn_w = (const float*)d_in[19];
    const float* dn_b = (const float*)d_in[20];
    const float* dn_lg= (const float*)d_in[21];
    const float* dn_lb= (const float*)d_in[22];
    float* out = (float*)d_out;

    float *h, *hg, *qk, *att, *ob, *hn, *up, *dn, *deg;
    int *starts, *pos; unsigned* adj;
    cudaGetSymbolAddress((void**)&h,   g_h);
    cudaGetSymbolAddress((void**)&hg,  g_hg);
    cudaGetSymbolAddress((void**)&qk,  g_qk);
    cudaGetSymbolAddress((void**)&att, g_att);
    cudaGetSymbolAddress((void**)&ob,  g_out);
    cudaGetSymbolAddress((void**)&hn,  g_hn);
    cudaGetSymbolAddress((void**)&up,  g_up);
    cudaGetSymbolAddress((void**)&dn,  g_dn);
    cudaGetSymbolAddress((void**)&deg, g_deg);
    cudaGetSymbolAddress((void**)&starts, g_starts);
    cudaGetSymbolAddress((void**)&pos,    g_pos);
    cudaGetSymbolAddress((void**)&adj,    g_adj);

    cudaFuncSetAttribute((const void*)gemm_tc<128,false>,
                         cudaFuncAttributeMaxDynamicSharedMemorySize, SMEM_128);
    cudaFuncSetAttribute((const void*)gemm_tc<128,true>,
                         cudaFuncAttributeMaxDynamicSharedMemorySize, SMEM_128);
    cudaFuncSetAttribute((const void*)gemm_tc<64,false>,
                         cudaFuncAttributeMaxDynamicSharedMemorySize, SMEM_64);

    // graph structure (first GEMM kept early so ncu -s 5 samples it)
    clear_adj_k<<<(int)((ADJTOT + 255)/256), 256>>>(adj);
    starts_k  <<<NN/256, 256>>>(batch, starts);
    pos_self_k<<<NN/256, 256>>>(batch, starts, pos, adj);

    // h = x @ W_in + b_in
    gemm_tc<128,false><<<dim3(HH/128, NN/BM, 1), 256, SMEM_128>>>(
        x, FF, 0, W_in, HH, 0, nullptr, nullptr, h, HH, 0, b_in, 0, FF, 0);

    edge_k    <<<EE/256, 256>>>(ei, batch, pos, adj);
    deg_k     <<<NN/256, 256>>>(batch, pos, adj, deg);

    for (int l = 0; l < LL; l++){
        gate_k<<<NN, 128>>>(h, deg, Wd + l*HH, bd + l*HH, hg);
        gemm_tc<128,false><<<dim3(HH/128, NN/BM, 1), 256, SMEM_128>>>(
            hg, HH, 0, Wqk + (size_t)l*HH*HH, HH, 0, nullptr, nullptr,
            qk, HH, 0, bqk + l*HH, 0, HH, FLAG_SIG);
        attn_k<<<NN/8, 256>>>(qk, hg, adj, starts, batch, att);
        // ob = att@Wl + hg@Wr + bl  (fused dual GEMM)
        gemm_tc<128,true><<<dim3(HH/128, NN/BM, 1), 256, SMEM_128>>>(
            att, HH, 0, Wl + (size_t)l*HH*HH, HH, 0,
            hg, Wr + (size_t)l*HH*HH,
            ob, HH, 0, bl + l*HH, 0, HH, 0);
        // fused: h = relu(l2norm(ob)); hn = LN(h)
        l2ln_k<<<NN, 128>>>(ob, h, hn, ln_g + l*HH, ln_b + l*HH);
        // grouped up: per group g: [N,64]@[64,256] + b, then LN(256)+relu
        gemm_tc<128,false><<<dim3(HFG/128, NN/BM, GG), 256, SMEM_128>>>(
            hn, HH, HG,
            up_w + (size_t)l*GG*HG*HFG, HFG, (long long)HG*HFG, nullptr, nullptr,
            up, HFF, HFG,
            up_b + (size_t)l*GG*HFG, HFG, HG, 0);
        ln_k<HFG, 128, true><<<NN*GG, 128>>>(up, up, up_lg + l*HFG, up_lb + l*HFG);
        // grouped down: per group g: [N,256]@[256,64] + b
        gemm_tc<64,false><<<dim3(1, NN/BM, GG), 256, SMEM_64>>>(
            up, HFF, HFG,
            dn_w + (size_t)l*GG*HFG*HG, HG, (long long)HFG*HG, nullptr, nullptr,
            dn, HH, HG,
            dn_b + (size_t)l*GG*HG, HG, HFG, 0);
        // fused: LN(64) + LayerScale residual into h
        ln_res_k<<<NN*GG, 64>>>(dn, h, dn_lg + l*HG, dn_lb + l*HG, gamma + l*HH);
    }

    pool_k<<<dim3(BB, HH/128), 128>>>(h, starts, out);
}

// round 10
// speedup vs baseline: 1.6196x; 1.1122x over previous
#include <cuda_runtime.h>
#include <cuda_bf16.h>
#include <mma.h>
#include <cstdint>
#include <math.h>

using namespace nvcuda;

// Problem constants (fixed instance)
#define NN    8192
#define BB    32
#define NMAX  512
#define FF    128
#define HH    512
#define LL    3
#define GG    8
#define HFF   2048
#define EE    131072
#define HG    (HH/GG)    // 64
#define HFG   (HFF/GG)   // 256
#define ADJW  16
#define ADJTOT ((size_t)BB*NMAX*ADJW)

#define FLAG_ACC 1
#define FLAG_SIG 2

// tf32 GEMM tiling
#define BM    128
#define BK    32
#define LDA_S 36
// bf16 GEMM tiling
#define BK64  64
#define LDA_E 72

typedef __nv_bfloat16 bf16;

// -------------------- scratch (device globals; no allocs) --------------------
__device__ __align__(16) float g_h  [NN*HH];
__device__ __align__(16) float g_hg [NN*HH];
__device__ __align__(16) float g_qk [NN*HH];
__device__ __align__(16) float g_att[NN*HH];
__device__ __align__(16) float g_out[NN*HH];
__device__ __align__(16) float g_up [NN*HFF];
__device__ __align__(16) float g_dn [NN*HH];
__device__ float    g_deg[NN];
__device__ int      g_starts[BB+1];
__device__ int      g_pos[NN];
__device__ unsigned g_adj[ADJTOT];
// bf16 FFN operands
__device__ __align__(16) bf16 g_hnb [NN*HH];
__device__ __align__(16) bf16 g_upb [NN*HFF];
__device__ __align__(16) bf16 g_upwb[LL*GG*HG*HFG];
__device__ __align__(16) bf16 g_dnwb[LL*GG*HFG*HG];

__device__ __forceinline__ float sigf(float x){ return 1.f/(1.f+__expf(-x)); }

__device__ __forceinline__ void cpa16p(float* s, const float* g){
    unsigned a = (unsigned)__cvta_generic_to_shared(s);
    asm volatile("cp.async.cg.shared.global [%0], [%1], 16;" :: "r"(a), "l"(g));
}
__device__ __forceinline__ void cpa16(uint32_t s, const void* g){
    asm volatile("cp.async.cg.shared.global [%0], [%1], 16;" :: "r"(s), "l"(g));
}
__device__ __forceinline__ void cpa_commit(){ asm volatile("cp.async.commit_group;"); }
template<int N> __device__ __forceinline__ void cpa_wait(){
    asm volatile("cp.async.wait_group %0;" :: "n"(N));
}
__device__ __forceinline__ uint32_t smem_u32(const void* p){
    uint32_t a;
    asm("{ .reg .u64 t; cvta.to.shared.u64 t, %1; cvt.u32.u64 %0, t; }" : "=r"(a) : "l"(p));
    return a;
}

// -------------------- fp32 -> bf16 (rn) bulk convert --------------------
__global__ void convert_k(const float* __restrict__ src, bf16* __restrict__ dst, int n){
    int i = (blockIdx.x*blockDim.x + threadIdx.x) * 4;
    if (i >= n) return;
    float4 v = *(const float4*)(src + i);
    __nv_bfloat162 p0 = __floats2bfloat162_rn(v.x, v.y);
    __nv_bfloat162 p1 = __floats2bfloat162_rn(v.z, v.w);
    *(uint2*)(dst + i) = make_uint2(*(uint32_t*)&p0, *(uint32_t*)&p1);
}

// -------------------- graph structure --------------------
__global__ void clear_adj_k(unsigned* __restrict__ adj){
    size_t i = (size_t)blockIdx.x*blockDim.x + threadIdx.x;
    if (i < ADJTOT) adj[i] = 0u;
}
__global__ void starts_k(const int* __restrict__ batch, int* __restrict__ starts){
    int n = blockIdx.x*blockDim.x + threadIdx.x;
    if (n >= NN) return;
    if (n == 0){ starts[batch[0]] = 0; starts[BB] = NN; }
    else if (batch[n] != batch[n-1]) starts[batch[n]] = n;
}
__global__ void pos_self_k(const int* __restrict__ batch, const int* __restrict__ starts,
                           int* __restrict__ pos, unsigned* __restrict__ adj){
    int n = blockIdx.x*blockDim.x + threadIdx.x;
    if (n >= NN) return;
    int b = batch[n];
    int p = n - starts[b];
    pos[n] = p;
    atomicOr(&adj[((size_t)b*NMAX + p)*ADJW + (p>>5)], 1u << (p&31));
}
__global__ void edge_k(const int* __restrict__ ei, const int* __restrict__ batch,
                       const int* __restrict__ pos, unsigned* __restrict__ adj){
    int e = blockIdx.x*blockDim.x + threadIdx.x;
    if (e >= EE) return;
    int s = ei[e];
    int d = ei[EE + e];
    int b = batch[s];
    atomicOr(&adj[((size_t)b*NMAX + pos[s])*ADJW + (pos[d]>>5)], 1u << (pos[d]&31));
}
__global__ void deg_k(const int* __restrict__ batch, const int* __restrict__ pos,
                      const unsigned* __restrict__ adj, float* __restrict__ deg){
    int n = blockIdx.x*blockDim.x + threadIdx.x;
    if (n >= NN) return;
    const unsigned* row = adj + ((size_t)batch[n]*NMAX + pos[n])*ADJW;
    int c = 0;
    #pragma unroll
    for (int w = 0; w < ADJW; w++) c += __popc(row[w]);
    deg[n] = (float)c;
}

// -------------------- TF32 tensor-core GEMM, 3-stage cp.async (main path) ----
template<int BN_, bool DUAL>
__global__ void __launch_bounds__(256, 2)
gemm_tc(const float* __restrict__ A, int lda, long long sAz,
        const float* __restrict__ W, int ldw, long long sWz,
        const float* __restrict__ A2, const float* __restrict__ W2,
        float*       __restrict__ C, int ldc, long long sCz,
        const float* __restrict__ bias, long long sBz,
        int K, int flags)
{
    constexpr int LDB  = BN_ + 4;
    constexpr int LDC_ = BN_ + 4;
    constexpr int ASZ  = BM * LDA_S;
    constexpr int BSZ  = BK * LDB;
    constexpr int STG  = ASZ + BSZ;
    constexpr int NF   = BN_ / 32;
    constexpr int BF4  = (BK * BN_) / 4 / 256;
    constexpr int BROW4= BN_ / 4;

    A += (size_t)blockIdx.z * sAz;
    W += (size_t)blockIdx.z * sWz;
    C += (size_t)blockIdx.z * sCz;
    if (bias) bias += (size_t)blockIdx.z * sBz;

    extern __shared__ __align__(16) float sm[];

    int tid  = threadIdx.x;
    int warp = tid >> 5;
    int wm   = warp >> 1;
    int wn   = warp & 1;
    int row0 = blockIdx.y * BM;
    int col0 = blockIdx.x * BN_;

    int ar  = tid >> 1,  ac0 = (tid & 1) * 16;

    wmma::fragment<wmma::accumulator, 16, 16, 8, float> acc[2][NF];
    #pragma unroll
    for (int i = 0; i < 2; i++)
        #pragma unroll
        for (int j = 0; j < NF; j++)
            wmma::fill_fragment(acc[i][j], 0.0f);

    const int T  = K / BK;
    const int TT = DUAL ? 2*T : T;

    auto prefetch = [&](int j){
        const float* Ap = (DUAL && j >= T) ? A2 : A;
        const float* Wp = (DUAL && j >= T) ? W2 : W;
        int k0 = (DUAL ? (j % T) : j) * BK;
        float* As = sm + (j % 3)*STG;
        float* Bs = As + ASZ;
        const float* ag = Ap + (size_t)(row0 + ar)*lda + k0 + ac0;
        #pragma unroll
        for (int i = 0; i < 4; i++) cpa16p(&As[ar*LDA_S + ac0 + i*4], ag + i*4);
        #pragma unroll
        for (int i = 0; i < BF4; i++){
            int f = tid + i*256;
            int brow = f / BROW4, bcol = (f % BROW4) * 4;
            cpa16p(&Bs[brow*LDB + bcol], Wp + (size_t)(k0 + brow)*ldw + col0 + bcol);
        }
        cpa_commit();
    };

    prefetch(0);
    if (TT > 1) prefetch(1);

    for (int it = 0; it < TT; it++){
        if (it + 1 < TT) cpa_wait<1>(); else cpa_wait<0>();
        __syncthreads();
        if (it + 2 < TT) prefetch(it + 2);

        float* As = sm + (it % 3)*STG;
        float* Bs = As + ASZ;
        #pragma unroll
        for (int kk = 0; kk < BK; kk += 8){
            wmma::fragment<wmma::matrix_a, 16, 16, 8, wmma::precision::tf32, wmma::row_major> fa[2];
            wmma::fragment<wmma::matrix_b, 16, 16, 8, wmma::precision::tf32, wmma::row_major> fb[NF];
            #pragma unroll
            for (int i = 0; i < 2; i++)
                wmma::load_matrix_sync(fa[i], &As[(wm*32 + i*16)*LDA_S + kk], LDA_S);
            #pragma unroll
            for (int j = 0; j < NF; j++)
                wmma::load_matrix_sync(fb[j], &Bs[kk*LDB + wn*(16*NF) + j*16], LDB);
            #pragma unroll
            for (int i = 0; i < 2; i++)
                #pragma unroll
                for (int j = 0; j < NF; j++)
                    wmma::mma_sync(acc[i][j], fa[i], fb[j], acc[i][j]);
        }
    }
    __syncthreads();

    #pragma unroll
    for (int i = 0; i < 2; i++)
        #pragma unroll
        for (int j = 0; j < NF; j++)
            wmma::store_matrix_sync(&sm[(wm*32 + i*16)*LDC_ + wn*(16*NF) + j*16],
                                    acc[i][j], LDC_, wmma::mem_row_major);
    __syncthreads();

    int er   = tid >> 1;
    int ecol = (tid & 1) * (BN_/2);
    #pragma unroll
    for (int i = 0; i < BN_/8; i++){
        int cc = ecol + i*4;
        float4 v = *(const float4*)&sm[er*LDC_ + cc];
        size_t gr = (size_t)(row0 + er)*ldc + col0 + cc;
        if (bias){
            v.x += bias[col0+cc+0]; v.y += bias[col0+cc+1];
            v.z += bias[col0+cc+2]; v.w += bias[col0+cc+3];
        }
        if (flags & FLAG_ACC){
            float4 c0 = *(const float4*)(C + gr);
            v.x += c0.x; v.y += c0.y; v.z += c0.z; v.w += c0.w;
        }
        if (flags & FLAG_SIG){
            v.x = sigf(v.x); v.y = sigf(v.y); v.z = sigf(v.z); v.w = sigf(v.w);
        }
        *(float4*)(C + gr) = v;
    }
}

#define T32_SMEM_128 (3*(BM*LDA_S + BK*(128+4))*(int)sizeof(float))   // 105984

// -------------------- bf16 tensor-core GEMM (FFN; LayerScale-damped) ---------
template<int BN_>
__global__ void __launch_bounds__(256, 2)
gemm_bf(const bf16* __restrict__ A, int lda, long long sAz,
        const bf16* __restrict__ W, int ldw, long long sWz,
        float* __restrict__ C, int ldc, long long sCz,
        const float* __restrict__ bias, long long sBz,
        int K)
{
    constexpr int LDB_E = BN_ + 8;
    constexpr int LDC_  = BN_ + 4;
    constexpr int ASZB  = BM * LDA_E * 2;
    constexpr int BSZB  = BK64 * LDB_E * 2;
    constexpr int STGB  = ASZB + BSZB;
    constexpr int NF    = BN_ / 32;
    constexpr int BROW8 = BN_ / 8;
    constexpr int BCH   = (BK64 * BROW8) / 256;

    A += (size_t)blockIdx.z * sAz;
    W += (size_t)blockIdx.z * sWz;
    C += (size_t)blockIdx.z * sCz;
    if (bias) bias += (size_t)blockIdx.z * sBz;

    extern __shared__ __align__(16) char smc[];

    int tid  = threadIdx.x;
    int warp = tid >> 5;
    int wm   = warp >> 1;
    int wn   = warp & 1;
    int row0 = blockIdx.y * BM;
    int col0 = blockIdx.x * BN_;

    wmma::fragment<wmma::accumulator, 16, 16, 16, float> acc[2][NF];
    #pragma unroll
    for (int i = 0; i < 2; i++)
        #pragma unroll
        for (int j = 0; j < NF; j++)
            wmma::fill_fragment(acc[i][j], 0.0f);

    const int T = K / BK64;

    auto prefetch = [&](int j){
        int k0 = j * BK64;
        uint32_t a0 = smem_u32(smc + (j % 3)*STGB);
        uint32_t b0 = a0 + ASZB;
        #pragma unroll
        for (int i = 0; i < 4; i++){
            int f = tid + i*256, r = f >> 3, c = f & 7;
            cpa16(a0 + r*(LDA_E*2) + c*16, A + (size_t)(row0+r)*lda + k0 + c*8);
        }
        #pragma unroll
        for (int i = 0; i < BCH; i++){
            int f = tid + i*256, r = f / BROW8, c = f % BROW8;
            cpa16(b0 + r*(LDB_E*2) + c*16, W + (size_t)(k0+r)*ldw + col0 + c*8);
        }
        cpa_commit();
    };

    prefetch(0);
    if (T > 1) prefetch(1);

    for (int it = 0; it < T; it++){
        if (it + 1 < T) cpa_wait<1>(); else cpa_wait<0>();
        __syncthreads();
        if (it + 2 < T) prefetch(it + 2);

        bf16* As = (bf16*)(smc + (it % 3)*STGB);
        bf16* Bs = (bf16*)(smc + (it % 3)*STGB + ASZB);
        #pragma unroll
        for (int kk = 0; kk < BK64; kk += 16){
            wmma::fragment<wmma::matrix_a, 16, 16, 16, bf16, wmma::row_major> fa[2];
            wmma::fragment<wmma::matrix_b, 16, 16, 16, bf16, wmma::row_major> fb[NF];
            #pragma unroll
            for (int i = 0; i < 2; i++)
                wmma::load_matrix_sync(fa[i], &As[(wm*32 + i*16)*LDA_E + kk], LDA_E);
            #pragma unroll
            for (int j = 0; j < NF; j++)
                wmma::load_matrix_sync(fb[j], &Bs[kk*LDB_E + wn*(16*NF) + j*16], LDB_E);
            #pragma unroll
            for (int i = 0; i < 2; i++)
                #pragma unroll
                for (int j = 0; j < NF; j++)
                    wmma::mma_sync(acc[i][j], fa[i], fb[j], acc[i][j]);
        }
    }
    __syncthreads();

    float* Cs = (float*)smc;
    #pragma unroll
    for (int i = 0; i < 2; i++)
        #pragma unroll
        for (int j = 0; j < NF; j++)
            wmma::store_matrix_sync(&Cs[(wm*32 + i*16)*LDC_ + wn*(16*NF) + j*16],
                                    acc[i][j], LDC_, wmma::mem_row_major);
    __syncthreads();

    int er   = tid >> 1;
    int ecol = (tid & 1) * (BN_/2);
    #pragma unroll
    for (int i = 0; i < BN_/8; i++){
        int cc = ecol + i*4;
        float4 v = *(const float4*)&Cs[er*LDC_ + cc];
        size_t gr = (size_t)(row0 + er)*ldc + col0 + cc;
        v.x += bias[col0+cc+0]; v.y += bias[col0+cc+1];
        v.z += bias[col0+cc+2]; v.w += bias[col0+cc+3];
        *(float4*)(C + gr) = v;
    }
}

#define BF_SMEM_128 (3*(BM*LDA_E*2 + BK64*(128+8)*2))   // 107520
#define BF_SMEM_64  (3*(BM*LDA_E*2 + BK64*(64+8)*2))    // 82944

// -------------------- elementwise / reductions --------------------
__global__ void gate_k(const float* __restrict__ h, const float* __restrict__ deg,
                       const float* __restrict__ Wd, const float* __restrict__ bd,
                       float* __restrict__ hg){
    int n = blockIdx.x, t = threadIdx.x;
    float d = deg[n];
    float4 hv = ((const float4*)(h + (size_t)n*HH))[t];
    float4 wv = ((const float4*)Wd)[t];
    float4 bv = ((const float4*)bd)[t];
    float4 o;
    o.x = hv.x * sigf(d*wv.x + bv.x);
    o.y = hv.y * sigf(d*wv.y + bv.y);
    o.z = hv.z * sigf(d*wv.z + bv.z);
    o.w = hv.w * sigf(d*wv.w + bv.w);
    ((float4*)(hg + (size_t)n*HH))[t] = o;
}

__global__ void attn_k(const float* __restrict__ qk, const float* __restrict__ hg,
                       const unsigned* __restrict__ adj, const int* __restrict__ starts,
                       const int* __restrict__ batch, float* __restrict__ out){
    int warp = (blockIdx.x*blockDim.x + threadIdx.x) >> 5;
    int lane = threadIdx.x & 31;
    if (warp >= NN) return;
    int n = warp;
    int b = batch[n];
    int start = starts[b];
    int p = n - start;
    const unsigned* row = adj + ((size_t)b*NMAX + p)*ADJW;
    const float4* qn4 = (const float4*)(qk + (size_t)n*HH);
    float4 qn[4];
    #pragma unroll
    for (int c = 0; c < 4; c++) qn[c] = qn4[lane + c*32];
    float4 acc[4] = {{0,0,0,0},{0,0,0,0},{0,0,0,0},{0,0,0,0}};
    float rowsum = 0.f;
    const float inv_sqrt_h = 0.044194173824159216f;
    for (int w = 0; w < ADJW; w++){
        unsigned bits = row[w];
        while (bits){
            int t = __ffs((int)bits) - 1; bits &= bits - 1;
            int m = start + w*32 + t;
            const float4* qm4 = (const float4*)(qk + (size_t)m*HH);
            float s = 0.f;
            #pragma unroll
            for (int c = 0; c < 4; c++){
                float4 v = qm4[lane + c*32];
                s += qn[c].x*v.x + qn[c].y*v.y + qn[c].z*v.z + qn[c].w*v.w;
            }
            #pragma unroll
            for (int o = 16; o; o >>= 1) s += __shfl_xor_sync(0xffffffffu, s, o);
            s *= inv_sqrt_h;
            rowsum += s;
            const float4* hm4 = (const float4*)(hg + (size_t)m*HH);
            #pragma unroll
            for (int c = 0; c < 4; c++){
                float4 hv = hm4[lane + c*32];
                acc[c].x += s*hv.x; acc[c].y += s*hv.y;
                acc[c].z += s*hv.z; acc[c].w += s*hv.w;
            }
        }
    }
    float inv = 1.f/(rowsum + 1e-6f);
    float4* o4 = (float4*)(out + (size_t)n*HH);
    #pragma unroll
    for (int c = 0; c < 4; c++){
        acc[c].x *= inv; acc[c].y *= inv; acc[c].z *= inv; acc[c].w *= inv;
        o4[lane + c*32] = acc[c];
    }
}

// fused: h = relu(l2norm(ob)); hnb = bf16(LN(h)*g+b)
__global__ void l2ln_k(const float* __restrict__ x, float* __restrict__ h,
                       bf16* __restrict__ hnb, const float* __restrict__ g,
                       const float* __restrict__ b){
    int n = blockIdx.x, t = threadIdx.x;
    float4 v = ((const float4*)(x + (size_t)n*HH))[t];
    float ss = v.x*v.x + v.y*v.y + v.z*v.z + v.w*v.w;
    #pragma unroll
    for (int o = 16; o; o >>= 1) ss += __shfl_xor_sync(0xffffffffu, ss, o);
    __shared__ float sh[4], sh2[4], red[3];
    int w = t >> 5, l = t & 31;
    if (l == 0) sh[w] = ss;
    __syncthreads();
    if (t == 0) red[0] = 1.f / fmaxf(sqrtf(sh[0]+sh[1]+sh[2]+sh[3]), 1e-12f);
    __syncthreads();
    float iv = red[0];
    float4 hv;
    hv.x = fmaxf(v.x*iv, 0.f); hv.y = fmaxf(v.y*iv, 0.f);
    hv.z = fmaxf(v.z*iv, 0.f); hv.w = fmaxf(v.w*iv, 0.f);
    ((float4*)(h + (size_t)n*HH))[t] = hv;
    float s  = hv.x + hv.y + hv.z + hv.w;
    float s2 = hv.x*hv.x + hv.y*hv.y + hv.z*hv.z + hv.w*hv.w;
    #pragma unroll
    for (int o = 16; o; o >>= 1){
        s  += __shfl_xor_sync(0xffffffffu, s,  o);
        s2 += __shfl_xor_sync(0xffffffffu, s2, o);
    }
    if (l == 0){ sh[w] = s; sh2[w] = s2; }
    __syncthreads();
    if (t == 0){
        float ts = sh[0]+sh[1]+sh[2]+sh[3], ts2 = sh2[0]+sh2[1]+sh2[2]+sh2[3];
        float mean = ts / HH;
        red[1] = mean; red[2] = rsqrtf(ts2/HH - mean*mean + 1e-5f);
    }
    __syncthreads();
    float mean = red[1], rstd = red[2];
    float4 gv = ((const float4*)g)[t];
    float4 bv = ((const float4*)b)[t];
    float4 o;
    o.x = (hv.x-mean)*rstd*gv.x + bv.x;
    o.y = (hv.y-mean)*rstd*gv.y + bv.y;
    o.z = (hv.z-mean)*rstd*gv.z + bv.z;
    o.w = (hv.w-mean)*rstd*gv.w + bv.w;
    __nv_bfloat162 p0 = __floats2bfloat162_rn(o.x, o.y);
    __nv_bfloat162 p1 = __floats2bfloat162_rn(o.z, o.w);
    ((uint2*)(hnb + (size_t)n*HH))[t] = make_uint2(*(uint32_t*)&p0, *(uint32_t*)&p1);
}

// LN(256)+relu over up rows, bf16 out (feeds dn GEMM only)
__global__ void ln_up_k(const float* __restrict__ x, bf16* __restrict__ y,
                        const float* __restrict__ g, const float* __restrict__ b){
    int row = blockIdx.x, t = threadIdx.x;
    const float* xr = x + (size_t)row*HFG;
    float v0 = xr[t], v1 = xr[t + 128];
    float s = v0 + v1, s2 = v0*v0 + v1*v1;
    #pragma unroll
    for (int o = 16; o; o >>= 1){
        s  += __shfl_xor_sync(0xffffffffu, s,  o);
        s2 += __shfl_xor_sync(0xffffffffu, s2, o);
    }
    __shared__ float sh[2][4], mb[2];
    int w = t >> 5, l = t & 31;
    if (l == 0){ sh[0][w] = s; sh[1][w] = s2; }
    __syncthreads();
    if (t == 0){
        float ts = sh[0][0]+sh[0][1]+sh[0][2]+sh[0][3];
        float ts2 = sh[1][0]+sh[1][1]+sh[1][2]+sh[1][3];
        float mean = ts / HFG;
        mb[0] = mean; mb[1] = rsqrtf(ts2/HFG - mean*mean + 1e-5f);
    }
    __syncthreads();
    float mean = mb[0], rstd = mb[1];
    bf16* yr = y + (size_t)row*HFG;
    float o0 = fmaxf((v0-mean)*rstd*g[t] + b[t], 0.f);
    float o1 = fmaxf((v1-mean)*rstd*g[t+128] + b[t+128], 0.f);
    yr[t]       = __float2bfloat16_rn(o0);
    yr[t + 128] = __float2bfloat16_rn(o1);
}

// fused: LN(64) over dn group-rows + LayerScale residual into h
__global__ void ln_res_k(const float* __restrict__ dnv, float* __restrict__ h,
                         const float* __restrict__ g, const float* __restrict__ b,
                         const float* __restrict__ gamma){
    int row = blockIdx.x;
    int t   = threadIdx.x;
    float u = dnv[(size_t)row*HG + t];
    float s = u, s2 = u*u;
    #pragma unroll
    for (int o = 16; o; o >>= 1){
        s  += __shfl_xor_sync(0xffffffffu, s,  o);
        s2 += __shfl_xor_sync(0xffffffffu, s2, o);
    }
    __shared__ float sa[2], sbv[2];
    int w = t >> 5, l = t & 31;
    if (l == 0){ sa[w] = s; sbv[w] = s2; }
    __syncthreads();
    float ts = sa[0]+sa[1], ts2 = sbv[0]+sbv[1];
    float mean = ts / HG;
    float rstd = rsqrtf(ts2/HG - mean*mean + 1e-5f);
    float o = (u - mean)*rstd*g[t] + b[t];
    int gi = (row & (GG-1))*HG + t;
    h[(size_t)row*HG + t] += gamma[gi]*o;
}

__global__ void pool_k(const float* __restrict__ h, const int* __restrict__ starts,
                       float* __restrict__ out){
    int b = blockIdx.x;
    int f = blockIdx.y*128 + threadIdx.x;
    int s = starts[b], e = starts[b+1];
    float acc = 0.f;
    for (int n = s; n < e; n++) acc += h[(size_t)n*HH + f];
    out[(size_t)b*HH + f] = acc;
}

// -------------------- launcher --------------------
extern "C" void kernel_launch(void* const* d_in, const int* in_sizes, int n_in,
                              void* d_out, int out_size){
    const float* x     = (const float*)d_in[0];
    const int*   ei    = (const int*)d_in[1];
    const int*   batch = (const int*)d_in[2];
    const float* W_in = (const float*)d_in[3];
    const float* b_in = (const float*)d_in[4];
    const float* Wqk  = (const float*)d_in[5];
    const float* bqk  = (const float*)d_in[6];
    const float* Wd   = (const float*)d_in[7];
    const float* bd   = (const float*)d_in[8];
    const float* Wl   = (const float*)d_in[9];
    const float* bl   = (const float*)d_in[10];
    const float* Wr   = (const float*)d_in[11];
    const float* gamma= (const float*)d_in[12];
    const float* ln_g = (const float*)d_in[13];
    const float* ln_b = (const float*)d_in[14];
    const float* up_w = (const float*)d_in[15];
    const float* up_b = (const float*)d_in[16];
    const float* up_lg= (const float*)d_in[17];
    const float* up_lb= (const float*)d_in[18];
    const float* dn_w = (const float*)d_in[19];
    const float* dn_b = (const float*)d_in[20];
    const float* dn_lg= (const float*)d_in[21];
    const float* dn_lb= (const float*)d_in[22];
    float* out = (float*)d_out;

    float *h, *hg, *qk, *att, *ob, *up, *dn, *deg;
    bf16 *hnb, *upb, *upwb, *dnwb;
    int *starts, *pos; unsigned* adj;
    cudaGetSymbolAddress((void**)&h,   g_h);
    cudaGetSymbolAddress((void**)&hg,  g_hg);
    cudaGetSymbolAddress((void**)&qk,  g_qk);
    cudaGetSymbolAddress((void**)&att, g_att);
    cudaGetSymbolAddress((void**)&ob,  g_out);
    cudaGetSymbolAddress((void**)&up,  g_up);
    cudaGetSymbolAddress((void**)&dn,  g_dn);
    cudaGetSymbolAddress((void**)&deg, g_deg);
    cudaGetSymbolAddress((void**)&starts, g_starts);
    cudaGetSymbolAddress((void**)&pos,    g_pos);
    cudaGetSymbolAddress((void**)&adj,    g_adj);
    cudaGetSymbolAddress((void**)&hnb,  g_hnb);
    cudaGetSymbolAddress((void**)&upb,  g_upb);
    cudaGetSymbolAddress((void**)&upwb, g_upwb);
    cudaGetSymbolAddress((void**)&dnwb, g_dnwb);

    cudaFuncSetAttribute((const void*)gemm_tc<128,false>,
                         cudaFuncAttributeMaxDynamicSharedMemorySize, T32_SMEM_128);
    cudaFuncSetAttribute((const void*)gemm_tc<128,true>,
                         cudaFuncAttributeMaxDynamicSharedMemorySize, T32_SMEM_128);
    cudaFuncSetAttribute((const void*)gemm_bf<128>,
                         cudaFuncAttributeMaxDynamicSharedMemorySize, BF_SMEM_128);
    cudaFuncSetAttribute((const void*)gemm_bf<64>,
                         cudaFuncAttributeMaxDynamicSharedMemorySize, BF_SMEM_64);

    // FFN weight conversions (bf16; LayerScale gamma damps their error)
    convert_k<<<LL*GG*HG*HFG/1024, 256>>>(up_w, upwb, LL*GG*HG*HFG);
    convert_k<<<LL*GG*HFG*HG/1024, 256>>>(dn_w, dnwb, LL*GG*HFG*HG);

    // graph structure
    clear_adj_k<<<(int)((ADJTOT + 255)/256), 256>>>(adj);
    starts_k  <<<NN/256, 256>>>(batch, starts);
    pos_self_k<<<NN/256, 256>>>(batch, starts, pos, adj);

    // h = x @ W_in + b_in   (tf32 main path)
    gemm_tc<128,false><<<dim3(HH/128, NN/BM, 1), 256, T32_SMEM_128>>>(
        x, FF, 0, W_in, HH, 0, nullptr, nullptr, h, HH, 0, b_in, 0, FF, 0);

    edge_k<<<EE/256, 256>>>(ei, batch, pos, adj);
    deg_k <<<NN/256, 256>>>(batch, pos, adj, deg);

    for (int l = 0; l < LL; l++){
        gate_k<<<NN, 128>>>(h, deg, Wd + l*HH, bd + l*HH, hg);
        gemm_tc<128,false><<<dim3(HH/128, NN/BM, 1), 256, T32_SMEM_128>>>(
            hg, HH, 0, Wqk + (size_t)l*HH*HH, HH, 0, nullptr, nullptr,
            qk, HH, 0, bqk + l*HH, 0, HH, FLAG_SIG);
        attn_k<<<NN/8, 256>>>(qk, hg, adj, starts, batch, att);
        // ob = att@Wl + hg@Wr + bl  (tf32 dual)
        gemm_tc<128,true><<<dim3(HH/128, NN/BM, 1), 256, T32_SMEM_128>>>(
            att, HH, 0, Wl + (size_t)l*HH*HH, HH, 0,
            hg, Wr + (size_t)l*HH*HH,
            ob, HH, 0, bl + l*HH, 0, HH, 0);
        l2ln_k<<<NN, 128>>>(ob, h, hnb, ln_g + l*HH, ln_b + l*HH);
        // grouped up (bf16): [N,64]@[64,256]
        gemm_bf<128><<<dim3(HFG/128, NN/BM, GG), 256, BF_SMEM_128>>>(
            hnb, HH, HG, upwb + (size_t)l*GG*HG*HFG, HFG, (long long)HG*HFG,
            up, HFF, HFG, up_b + (size_t)l*GG*HFG, HFG, 64);
        ln_up_k<<<NN*GG, 128>>>(up, upb, up_lg + l*HFG, up_lb + l*HFG);
        // grouped down (bf16): [N,256]@[256,64]
        gemm_bf<64><<<dim3(1, NN/BM, GG), 256, BF_SMEM_64>>>(
            upb, HFF, HFG, dnwb + (size_t)l*GG*HFG*HG, HG, (long long)HFG*HG,
            dn, HH, HG, dn_b + (size_t)l*GG*HG, HG, 256);
        ln_res_k<<<NN*GG, 64>>>(dn, h, dn_lg + l*HG, dn_lb + l*HG, gamma + l*HH);
    }

    pool_k<<<dim3(BB, HH/128), 128>>>(h, starts, out);
}